// round 12
// baseline (speedup 1.0000x reference)
#include <cuda_runtime.h>
#include <cuda_bf16.h>
#include <cuda_fp16.h>
#include <cstdint>
#include <math.h>

#define Nn 50000
#define Rr 4
#define Ee 1600000
#define Hh 256
#define Cc 16
#define NBLK 13   // ceil(50000 / 4096)

// ---------------- scratch (device globals; no runtime allocation) ----------
__device__ int   g_deg_r[Rr * Nn];
__device__ int   g_deg_c[Rr * Nn];
__device__ float g_dinv_r[Rr * Nn];
__device__ float g_dinv_c[Rr * Nn];
__device__ int   g_row_ptr[Rr * (Nn + 1)];
__device__ int   g_cursor[Rr * Nn];
__device__ int   g_blksum[Rr * NBLK];
__device__ int2  g_edge[(size_t)Rr * Ee];   // packed {col, wgt_bits}
// fp16 gather sources
__device__ __half g_Xh[(size_t)Nn * Hh];
__device__ __half g_h1h[(size_t)Nn * Hh];
// SpMM outputs packed fp16: [R][N][256] fp16 = 32 uint4 per row
__device__ uint4 g_S16[(size_t)Rr * Nn * 32];
// bf16 hi/lo split of W transposed to n-major: [layer][R][n=256][k=256]
__device__ uint4 g_Bhi[2 * Rr * 256 * 32];
__device__ uint4 g_Blo[2 * Rr * 256 * 32];
__device__ float g_H[(size_t)Rr * Nn * Hh];

// ---------------- low-level helpers (all base-arch PTX) ---------------------
__device__ __forceinline__ uint32_t smem_to_u32(const void* p) {
    uint32_t a;
    asm("{ .reg .u64 t; cvta.to.shared.u64 t, %1; cvt.u32.u64 %0, t; }" : "=r"(a) : "l"(p));
    return a;
}
__device__ __forceinline__ void cp16(uint32_t dst, const void* src, int sz) {
    asm volatile("cp.async.cg.shared.global [%0], [%1], 16, %2;"
                 :: "r"(dst), "l"(src), "r"(sz));
}
__device__ __forceinline__ void ldsm4(uint32_t* r, uint32_t addr) {
    asm volatile("ldmatrix.sync.aligned.m8n8.x4.shared.b16 {%0,%1,%2,%3}, [%4];"
                 : "=r"(r[0]), "=r"(r[1]), "=r"(r[2]), "=r"(r[3]) : "r"(addr));
}
__device__ __forceinline__ void mma16816(float* c, const uint32_t* a, uint32_t b0, uint32_t b1) {
    asm volatile("mma.sync.aligned.m16n8k16.row.col.f32.bf16.bf16.f32 "
                 "{%0,%1,%2,%3}, {%4,%5,%6,%7}, {%8,%9}, {%0,%1,%2,%3};"
                 : "+f"(c[0]), "+f"(c[1]), "+f"(c[2]), "+f"(c[3])
                 : "r"(a[0]), "r"(a[1]), "r"(a[2]), "r"(a[3]), "r"(b0), "r"(b1));
}

// ---------------- bf16 split helpers ----------------------------------------
__device__ __forceinline__ void split2(float x, unsigned short& h, unsigned short& l) {
    __nv_bfloat16 hb = __float2bfloat16(x);
    h = __bfloat16_as_ushort(hb);
    l = __bfloat16_as_ushort(__float2bfloat16(x - __bfloat162float(hb)));
}
// 8 fp16 -> 8 bf16 hi + 8 bf16 lo
__device__ __forceinline__ void cvt_hilo(uint4 s, uint4& vh, uint4& vl) {
    const __half2* hp = (const __half2*)&s;
    unsigned short* hh = (unsigned short*)&vh;
    unsigned short* ll = (unsigned short*)&vl;
#pragma unroll
    for (int i = 0; i < 4; i++) {
        float2 f = __half22float2(hp[i]);
        unsigned short h0, l0, h1, l1;
        split2(f.x, h0, l0);
        split2(f.y, h1, l1);
        hh[2 * i] = h0; hh[2 * i + 1] = h1;
        ll[2 * i] = l0; ll[2 * i + 1] = l1;
    }
}

// ---------------- CSR construction ------------------------------------------
__global__ void k_zero_deg() {
    int i = blockIdx.x * blockDim.x + threadIdx.x;
    if (i < Rr * Nn) { g_deg_r[i] = 0; g_deg_c[i] = 0; }
}
__global__ void k_hist(const int* __restrict__ ei) {
    int idx = blockIdx.x * blockDim.x + threadIdx.x;
    if (idx >= Rr * Ee) return;
    int r = idx / Ee, e = idx - r * Ee;
    const int* base = ei + (size_t)r * 2 * Ee;
    atomicAdd(&g_deg_r[r * Nn + base[e]], 1);
    atomicAdd(&g_deg_c[r * Nn + base[Ee + e]], 1);
}
__global__ void k_dinv() {
    int i = blockIdx.x * blockDim.x + threadIdx.x;
    if (i >= Rr * Nn) return;
    g_dinv_r[i] = rsqrtf(fmaxf((float)g_deg_r[i], 1.0f));
    g_dinv_c[i] = rsqrtf(fmaxf((float)g_deg_c[i], 1.0f));
}

// ---- multi-block scan ---------------------------------------------------
__global__ __launch_bounds__(1024) void k_scan1() {
    int r = blockIdx.y, b = blockIdx.x;
    int t = threadIdx.x, lane = t & 31, w = t >> 5;
    __shared__ int wsum[32];
    int i0 = b * 4096 + t * 4;
    int v[4], s = 0;
#pragma unroll
    for (int j = 0; j < 4; j++) {
        v[j] = (i0 + j < Nn) ? g_deg_r[r * Nn + i0 + j] : 0;
        s += v[j];
    }
    int x = s;
#pragma unroll
    for (int o = 1; o < 32; o <<= 1) {
        int y = __shfl_up_sync(0xffffffffu, x, o);
        if (lane >= o) x += y;
    }
    if (lane == 31) wsum[w] = x;
    __syncthreads();
    if (w == 0) {
        int s2 = wsum[lane];
#pragma unroll
        for (int o = 1; o < 32; o <<= 1) {
            int y = __shfl_up_sync(0xffffffffu, s2, o);
            if (lane >= o) s2 += y;
        }
        wsum[lane] = s2;
    }
    __syncthreads();
    int woff = (w == 0) ? 0 : wsum[w - 1];
    int run = woff + x - s;
#pragma unroll
    for (int j = 0; j < 4; j++) {
        if (i0 + j < Nn) g_row_ptr[r * (Nn + 1) + i0 + j] = run;
        run += v[j];
    }
    if (t == 1023) g_blksum[r * NBLK + b] = woff + x;
}
__global__ void k_scan2() {
    int t = threadIdx.x, lane = t & 31, w = t >> 5;
    int v = (lane < NBLK) ? g_blksum[w * NBLK + lane] : 0;
    int x = v;
#pragma unroll
    for (int o = 1; o < 32; o <<= 1) {
        int y = __shfl_up_sync(0xffffffffu, x, o);
        if (lane >= o) x += y;
    }
    if (lane < NBLK) g_blksum[w * NBLK + lane] = x - v;
    if (lane == NBLK - 1) g_row_ptr[w * (Nn + 1) + Nn] = x;
}
__global__ __launch_bounds__(1024) void k_scan3() {
    int r = blockIdx.y, b = blockIdx.x;
    int off = g_blksum[r * NBLK + b];
    int i0 = b * 4096 + threadIdx.x * 4;
#pragma unroll
    for (int j = 0; j < 4; j++) {
        int i = i0 + j;
        if (i < Nn) {
            int p = g_row_ptr[r * (Nn + 1) + i] + off;
            g_row_ptr[r * (Nn + 1) + i] = p;
            g_cursor[r * Nn + i] = p;
        }
    }
}

__global__ void k_scatter(const int* __restrict__ ei) {
    int idx = blockIdx.x * blockDim.x + threadIdx.x;
    if (idx >= Rr * Ee) return;
    int r = idx / Ee, e = idx - r * Ee;
    const int* base = ei + (size_t)r * 2 * Ee;
    int row = base[e];
    int col = base[Ee + e];
    int pos = atomicAdd(&g_cursor[r * Nn + row], 1);
    float w = g_dinv_r[r * Nn + row] * g_dinv_c[r * Nn + col];
    g_edge[(size_t)r * Ee + pos] = make_int2(col, __float_as_int(w));
}

// ---------------- fp32 -> fp16 conversion ------------------------------------
__global__ void k_cvt(const float* __restrict__ x, __half* __restrict__ dst) {
    int idx = blockIdx.x * blockDim.x + threadIdx.x;
    const int total = Nn * Hh / 4;
    if (idx >= total) return;
    float4 v = ((const float4*)x)[idx];
    __half2 p0 = __floats2half2_rn(v.x, v.y);
    __half2 p1 = __floats2half2_rn(v.z, v.w);
    uint2 u;
    u.x = *(const uint32_t*)&p0;
    u.y = *(const uint32_t*)&p1;
    ((uint2*)dst)[idx] = u;
}

// ---------------- SpMM: warp per row, fp16 gather, 4-edge pipelined ---------
__device__ __forceinline__ void fma8(float* acc, float w, const uint4& v) {
    const __half2* h = (const __half2*)&v;
    float2 f;
    f = __half22float2(h[0]); acc[0] += w * f.x; acc[1] += w * f.y;
    f = __half22float2(h[1]); acc[2] += w * f.x; acc[3] += w * f.y;
    f = __half22float2(h[2]); acc[4] += w * f.x; acc[5] += w * f.y;
    f = __half22float2(h[3]); acc[6] += w * f.x; acc[7] += w * f.y;
}

__global__ __launch_bounds__(256) void k_spmm(int use_h1, int r) {
    int n = blockIdx.x * 8 + (threadIdx.x >> 5);
    if (n >= Nn) return;
    int lane = threadIdx.x & 31;
    const uint4* __restrict__ src = (const uint4*)(use_h1 ? g_h1h : g_Xh);
    int beg = g_row_ptr[r * (Nn + 1) + n];
    int end = g_row_ptr[r * (Nn + 1) + n + 1];
    const int2* __restrict__ edges = g_edge + (size_t)r * Ee;
    float acc[8];
#pragma unroll
    for (int j = 0; j < 8; j++) acc[j] = 0.f;

    int e = beg;
    for (; e + 4 <= end; e += 4) {
        int2 d0 = __ldg(edges + e);
        int2 d1 = __ldg(edges + e + 1);
        int2 d2 = __ldg(edges + e + 2);
        int2 d3 = __ldg(edges + e + 3);
        uint4 v0 = __ldg(src + ((size_t)d0.x << 5) + lane);
        uint4 v1 = __ldg(src + ((size_t)d1.x << 5) + lane);
        uint4 v2 = __ldg(src + ((size_t)d2.x << 5) + lane);
        uint4 v3 = __ldg(src + ((size_t)d3.x << 5) + lane);
        fma8(acc, __int_as_float(d0.y), v0);
        fma8(acc, __int_as_float(d1.y), v1);
        fma8(acc, __int_as_float(d2.y), v2);
        fma8(acc, __int_as_float(d3.y), v3);
    }
    for (; e < end; ++e) {
        int2 d = __ldg(edges + e);
        uint4 v = __ldg(src + ((size_t)d.x << 5) + lane);
        fma8(acc, __int_as_float(d.y), v);
    }

    __half2 p0 = __floats2half2_rn(acc[0], acc[1]);
    __half2 p1 = __floats2half2_rn(acc[2], acc[3]);
    __half2 p2 = __floats2half2_rn(acc[4], acc[5]);
    __half2 p3 = __floats2half2_rn(acc[6], acc[7]);
    uint4 o;
    o.x = *(const uint32_t*)&p0; o.y = *(const uint32_t*)&p1;
    o.z = *(const uint32_t*)&p2; o.w = *(const uint32_t*)&p3;
    g_S16[((size_t)r * Nn + n) * 32 + lane] = o;
}

// ---------------- W split+transpose into [layer] slot ------------------------
__global__ void k_splitW(const float* __restrict__ W, int layer) {
    int idx = blockIdx.x * blockDim.x + threadIdx.x;
    if (idx >= Rr * 256 * 256) return;
    int r = idx >> 16;
    int n = (idx >> 8) & 255;
    int k = idx & 255;
    float w = W[((size_t)r << 16) + ((size_t)k << 8) + n];
    unsigned short h, l;
    split2(w, h, l);
    size_t o = ((size_t)(layer * Rr + r) << 16) + ((size_t)n << 8) + k;
    ((unsigned short*)g_Bhi)[o] = h;
    ((unsigned short*)g_Blo)[o] = l;
}

// ---------------- GEMM: H[r] = ReLU(S[r] @ W[layer][r]), fp16 A, fp32 out ---
#define A_STRIDE 72
#define B_STRIDE 264
#define ASZ (128 * A_STRIDE * 2)
#define SM_B_HI 0
#define SM_B_LO (128 * B_STRIDE * 2)
#define SM_A0   (2 * 128 * B_STRIDE * 2)
#define SMEM_GEMM (SM_A0 + 4 * ASZ)

__global__ __launch_bounds__(256) void k_gemm(int layer, int r) {
    extern __shared__ char smem[];
    uint32_t sb = smem_to_u32(smem);
    int tid = threadIdx.x, lane = tid & 31, wid = tid >> 5;
    int wm = wid >> 1, wn = wid & 1;
    int m0 = blockIdx.x * 128, n0 = blockIdx.y * 128;

    {
        const uint4* bh = g_Bhi + ((size_t)((layer * Rr + r) * 256 + n0)) * 32;
        const uint4* bl = g_Blo + ((size_t)((layer * Rr + r) * 256 + n0)) * 32;
#pragma unroll
        for (int j = 0; j < 16; j++) {
            int lin = tid + j * 256;
            int row = lin >> 5, ch = lin & 31;
            uint32_t so = row * (B_STRIDE * 2) + ch * 16;
            cp16(sb + SM_B_HI + so, bh + row * 32 + ch, 16);
            cp16(sb + SM_B_LO + so, bl + row * 32 + ch, 16);
        }
    }
    asm volatile("cp.async.commit_group;" ::: "memory");

    uint4 stage[4];
    auto loadA = [&](int kc) {
#pragma unroll
        for (int j = 0; j < 4; j++) {
            int lin = tid + j * 256;
            int row = lin >> 3, ch = lin & 7;
            int gm = m0 + row;
            int gmc = (gm < Nn) ? gm : (Nn - 1);
            stage[j] = __ldg(g_S16 + ((size_t)r * Nn + gmc) * 32 + kc * 8 + ch);
        }
    };
    auto stsA = [&](int kc) {
        char* abase = smem + SM_A0 + (kc & 1) * 2 * ASZ;
#pragma unroll
        for (int j = 0; j < 4; j++) {
            int lin = tid + j * 256;
            int row = lin >> 3, ch = lin & 7;
            uint4 vh, vl;
            cvt_hilo(stage[j], vh, vl);
            uint32_t so = row * (A_STRIDE * 2) + ch * 16;
            *(uint4*)(abase + so) = vh;
            *(uint4*)(abase + ASZ + so) = vl;
        }
    };

    loadA(0);

    float acc[2][8][4];
#pragma unroll
    for (int a = 0; a < 2; a++)
#pragma unroll
        for (int b = 0; b < 8; b++)
#pragma unroll
            for (int c = 0; c < 4; c++) acc[a][b][c] = 0.f;

    int krow = lane & 15;
    int kof  = (lane >> 4) * 8;

    for (int kc = 0; kc < 4; kc++) {
        stsA(kc);
        if (kc == 0) asm volatile("cp.async.wait_group 0;" ::: "memory");
        if (kc < 3) loadA(kc + 1);
        __syncthreads();

        uint32_t ahb = sb + SM_A0 + (kc & 1) * 2 * ASZ;
        uint32_t alb = ahb + ASZ;
#pragma unroll
        for (int kk = 0; kk < 4; kk++) {
            uint32_t ahi[2][4], alo[2][4], bhi[4][4], blo[4][4];
            uint32_t a_off = (wm * 32 + krow) * (A_STRIDE * 2) + (kk * 16 + kof) * 2;
            ldsm4(ahi[0], ahb + a_off);
            ldsm4(ahi[1], ahb + a_off + 16 * (A_STRIDE * 2));
            ldsm4(alo[0], alb + a_off);
            ldsm4(alo[1], alb + a_off + 16 * (A_STRIDE * 2));
            int kg = kc * 64 + kk * 16 + kof;
#pragma unroll
            for (int nq = 0; nq < 4; nq++) {
                uint32_t b_off = (wn * 64 + nq * 16 + krow) * (B_STRIDE * 2) + kg * 2;
                ldsm4(bhi[nq], sb + SM_B_HI + b_off);
                ldsm4(blo[nq], sb + SM_B_LO + b_off);
            }
#pragma unroll
            for (int mt = 0; mt < 2; mt++) {
#pragma unroll
                for (int nq = 0; nq < 4; nq++) {
                    float* cl = acc[mt][nq * 2];
                    float* ch = acc[mt][nq * 2 + 1];
                    mma16816(cl, ahi[mt], bhi[nq][0], bhi[nq][2]);
                    mma16816(ch, ahi[mt], bhi[nq][1], bhi[nq][3]);
                    mma16816(cl, ahi[mt], blo[nq][0], blo[nq][2]);
                    mma16816(ch, ahi[mt], blo[nq][1], blo[nq][3]);
                    mma16816(cl, alo[mt], bhi[nq][0], bhi[nq][2]);
                    mma16816(ch, alo[mt], bhi[nq][1], bhi[nq][3]);
                }
            }
        }
        __syncthreads();
    }

    int gm_base = m0 + wm * 32 + (lane >> 2);
    int gn_base = n0 + wn * 64 + (lane & 3) * 2;
#pragma unroll
    for (int mt = 0; mt < 2; mt++) {
#pragma unroll
        for (int nn = 0; nn < 8; nn++) {
            float* c = acc[mt][nn];
            int gm = gm_base + mt * 16;
            int gn = gn_base + nn * 8;
            if (gm < Nn) {
                float2 v = make_float2(fmaxf(c[0], 0.f), fmaxf(c[1], 0.f));
                *(float2*)(g_H + ((size_t)r * Nn + gm) * Hh + gn) = v;
            }
            if (gm + 8 < Nn) {
                float2 v = make_float2(fmaxf(c[2], 0.f), fmaxf(c[3], 0.f));
                *(float2*)(g_H + ((size_t)r * Nn + gm + 8) * Hh + gn) = v;
            }
        }
    }
}

// ---------------- layer-1 mean: h1 = 0.25 * sum_r H[r] -> fp16 --------------
__global__ void k_mean() {
    int idx = blockIdx.x * blockDim.x + threadIdx.x;
    const int total = Nn * Hh / 4;
    if (idx >= total) return;
    const float4* h = (const float4*)g_H;
    size_t off = (size_t)Nn * Hh / 4;
    float4 a = h[idx], b = h[idx + off], c = h[idx + 2 * off], d = h[idx + 3 * off];
    float4 m;
    m.x = 0.25f * (a.x + b.x + c.x + d.x);
    m.y = 0.25f * (a.y + b.y + c.y + d.y);
    m.z = 0.25f * (a.z + b.z + c.z + d.z);
    m.w = 0.25f * (a.w + b.w + c.w + d.w);
    __half2 p0 = __floats2half2_rn(m.x, m.y);
    __half2 p1 = __floats2half2_rn(m.z, m.w);
    uint2 u;
    u.x = *(const uint32_t*)&p0;
    u.y = *(const uint32_t*)&p1;
    ((uint2*)g_h1h)[idx] = u;
}

// ---------------- attention + residual fusion + output GEMM -----------------
__global__ __launch_bounds__(256) void k_attn(const float* __restrict__ att_q,
                                              const float* __restrict__ tau_p,
                                              const float* __restrict__ W_out,
                                              const float* __restrict__ b_out,
                                              float* __restrict__ out) {
    int n = blockIdx.x * 8 + (threadIdx.x >> 5);
    if (n >= Nn) return;
    int lane = threadIdx.x & 31;

    float q[8];
#pragma unroll
    for (int k = 0; k < 8; k++) q[k] = att_q[lane + 32 * k];

    float v[4][8];
    float sc[4];
#pragma unroll
    for (int r = 0; r < 4; r++) {
        const float* h = g_H + ((size_t)r * Nn + n) * Hh;
        float s = 0.f;
#pragma unroll
        for (int k = 0; k < 8; k++) {
            v[r][k] = h[lane + 32 * k];
            s += v[r][k] * q[k];
        }
#pragma unroll
        for (int o = 16; o; o >>= 1) s += __shfl_xor_sync(0xffffffffu, s, o);
        sc[r] = s;
    }
    float tc = fminf(fmaxf(tau_p[0], 0.5f), 5.0f);
    float inv = 1.0f / tc;
    float s0 = sc[0] * inv, s1 = sc[1] * inv, s2 = sc[2] * inv, s3 = sc[3] * inv;
    float m = fmaxf(fmaxf(s0, s1), fmaxf(s2, s3));
    float e0 = expf(s0 - m), e1 = expf(s1 - m), e2 = expf(s2 - m), e3 = expf(s3 - m);
    float se = e0 + e1 + e2 + e3;
    float al[4] = {e0 / se, e1 / se, e2 / se, e3 / se};

    float h2[8];
#pragma unroll
    for (int k = 0; k < 8; k++)
        h2[k] = (0.25f + al[0]) * v[0][k] + (0.25f + al[1]) * v[1][k] +
                (0.25f + al[2]) * v[2][k] + (0.25f + al[3]) * v[3][k];

    float acc[16];
#pragma unroll
    for (int c = 0; c < 16; c++) acc[c] = 0.f;
#pragma unroll
    for (int k = 0; k < 8; k++) {
        int idx = lane + 32 * k;
        const float4* wr = (const float4*)(W_out + (size_t)idx * 16);
        float4 w0 = wr[0], w1 = wr[1], w2 = wr[2], w3 = wr[3];
        float hv = h2[k];
        acc[0]  += hv * w0.x; acc[1]  += hv * w0.y; acc[2]  += hv * w0.z; acc[3]  += hv * w0.w;
        acc[4]  += hv * w1.x; acc[5]  += hv * w1.y; acc[6]  += hv * w1.z; acc[7]  += hv * w1.w;
        acc[8]  += hv * w2.x; acc[9]  += hv * w2.y; acc[10] += hv * w2.z; acc[11] += hv * w2.w;
        acc[12] += hv * w3.x; acc[13] += hv * w3.y; acc[14] += hv * w3.z; acc[15] += hv * w3.w;
    }
#pragma unroll
    for (int c = 0; c < 16; c++)
#pragma unroll
        for (int o = 16; o; o >>= 1) acc[c] += __shfl_xor_sync(0xffffffffu, acc[c], o);

    if (lane < 16) {
        float lg = 0.f;
#pragma unroll
        for (int c = 0; c < 16; c++)
            if (lane == c) lg = acc[c];
        out[(size_t)n * Cc + lane] = lg + b_out[lane];
    }
    if (lane < 4) {
        float a = al[0];
        if (lane == 1) a = al[1];
        if (lane == 2) a = al[2];
        if (lane == 3) a = al[3];
        out[(size_t)Nn * Cc + (size_t)n * Rr + lane] = a;
    }
}

// ---------------- launch (dual-stream pipelined, capture-legal fork) ---------
extern "C" void kernel_launch(void* const* d_in, const int* in_sizes, int n_in,
                              void* d_out, int out_size) {
    const float* X     = (const float*)d_in[0];
    const int*   EI    = (const int*)d_in[1];
    const float* W1    = (const float*)d_in[2];
    const float* W2    = (const float*)d_in[3];
    const float* att_q = (const float*)d_in[4];
    const float* tau   = (const float*)d_in[5];
    const float* W_out = (const float*)d_in[6];
    const float* b_out = (const float*)d_in[7];
    float* out = (float*)d_out;
    (void)in_sizes; (void)n_in; (void)out_size;

    // one-time host-side setup (streams/events; no device memory)
    static cudaStream_t s1 = nullptr;
    static cudaEvent_t evFork, evPrep, evS1[Rr], evMean, evS2[Rr], evDone;
    if (s1 == nullptr) {
        cudaStreamCreateWithFlags(&s1, cudaStreamNonBlocking);
        cudaEventCreateWithFlags(&evFork, cudaEventDisableTiming);
        cudaEventCreateWithFlags(&evPrep, cudaEventDisableTiming);
        cudaEventCreateWithFlags(&evMean, cudaEventDisableTiming);
        cudaEventCreateWithFlags(&evDone, cudaEventDisableTiming);
        for (int r = 0; r < Rr; r++) {
            cudaEventCreateWithFlags(&evS1[r], cudaEventDisableTiming);
            cudaEventCreateWithFlags(&evS2[r], cudaEventDisableTiming);
        }
        cudaFuncSetAttribute(k_gemm, cudaFuncAttributeMaxDynamicSharedMemorySize, SMEM_GEMM);
    }

    __half* xh;
    cudaGetSymbolAddress((void**)&xh, g_Xh);

    dim3 spmm_grid((Nn + 7) / 8);
    dim3 gemm_grid((Nn + 127) / 128, Hh / 128);

    // --- fork s1 FROM the captured origin stream (capture-legal) -----------
    k_zero_deg<<<(Rr * Nn + 255) / 256, 256>>>();
    cudaEventRecord(evFork, 0);
    cudaStreamWaitEvent(s1, evFork, 0);

    // --- stream 0: CSR chain ---
    k_hist<<<(Rr * Ee + 255) / 256, 256>>>(EI);
    k_dinv<<<(Rr * Nn + 255) / 256, 256>>>();
    k_scan1<<<dim3(NBLK, Rr), 1024>>>();
    k_scan2<<<1, 128>>>();
    k_scan3<<<dim3(NBLK, Rr), 1024>>>();
    k_scatter<<<(Rr * Ee + 255) / 256, 256>>>(EI);

    // --- stream 1: prep (cvt + both weight splits) concurrently -------------
    k_cvt<<<(Nn * Hh / 4 + 255) / 256, 256, 0, s1>>>(X, xh);
    k_splitW<<<(Rr * 256 * 256 + 255) / 256, 256, 0, s1>>>(W1, 0);
    k_splitW<<<(Rr * 256 * 256 + 255) / 256, 256, 0, s1>>>(W2, 1);
    cudaEventRecord(evPrep, s1);
    cudaStreamWaitEvent(0, evPrep, 0);

    // --- layer 1: per-relation SpMM on s0, GEMM pipelined on s1 -------------
    for (int r = 0; r < Rr; r++) {
        k_spmm<<<spmm_grid, 256>>>(0, r);
        cudaEventRecord(evS1[r], 0);
        cudaStreamWaitEvent(s1, evS1[r], 0);
        k_gemm<<<gemm_grid, 256, SMEM_GEMM, s1>>>(0, r);
    }
    k_mean<<<(Nn * Hh / 4 + 255) / 256, 256, 0, s1>>>();
    cudaEventRecord(evMean, s1);
    cudaStreamWaitEvent(0, evMean, 0);

    // --- layer 2: same pipeline -------------------------------------------
    for (int r = 0; r < Rr; r++) {
        k_spmm<<<spmm_grid, 256>>>(1, r);
        cudaEventRecord(evS2[r], 0);
        cudaStreamWaitEvent(s1, evS2[r], 0);
        k_gemm<<<gemm_grid, 256, SMEM_GEMM, s1>>>(1, r);
    }
    k_attn<<<(Nn + 7) / 8, 256, 0, s1>>>(att_q, tau, W_out, b_out, out);
    cudaEventRecord(evDone, s1);
    cudaStreamWaitEvent(0, evDone, 0);
}

// round 13
// speedup vs baseline: 1.2370x; 1.2370x over previous
#include <cuda_runtime.h>
#include <cuda_bf16.h>
#include <cuda_fp16.h>
#include <cstdint>
#include <math.h>

#define Nn 50000
#define Rr 4
#define Ee 1600000
#define Hh 256
#define Cc 16
#define NBLK 13   // ceil(50000 / 4096)

// ---------------- scratch (device globals; no runtime allocation) ----------
__device__ int   g_deg_r[Rr * Nn];
__device__ int   g_deg_c[Rr * Nn];
__device__ float g_dinv_r[Rr * Nn];
__device__ float g_dinv_c[Rr * Nn];
__device__ int   g_row_ptr[Rr * (Nn + 1)];
__device__ int   g_cursor[Rr * Nn];
__device__ int   g_blksum[Rr * NBLK];
__device__ int2  g_edge[(size_t)Rr * Ee];   // packed {col, wgt_bits}
// fp16 gather sources
__device__ __half g_Xh[(size_t)Nn * Hh];
__device__ __half g_h1h[(size_t)Nn * Hh];
// SpMM outputs packed fp16: [R][N][256] fp16 = 32 uint4 per row
__device__ uint4 g_S16[(size_t)Rr * Nn * 32];
// fp16 hi/lo split of W transposed to n-major: [R][n=256][k=256]
__device__ uint4 g_Bhi[Rr * 256 * 32];
__device__ uint4 g_Blo[Rr * 256 * 32];
__device__ float g_H[(size_t)Rr * Nn * Hh];

// ---------------- low-level helpers (all base-arch PTX) ---------------------
__device__ __forceinline__ uint32_t smem_to_u32(const void* p) {
    uint32_t a;
    asm("{ .reg .u64 t; cvta.to.shared.u64 t, %1; cvt.u32.u64 %0, t; }" : "=r"(a) : "l"(p));
    return a;
}
__device__ __forceinline__ void cp16(uint32_t dst, const void* src, int sz) {
    asm volatile("cp.async.cg.shared.global [%0], [%1], 16, %2;"
                 :: "r"(dst), "l"(src), "r"(sz));
}
__device__ __forceinline__ void ldsm4(uint32_t* r, uint32_t addr) {
    asm volatile("ldmatrix.sync.aligned.m8n8.x4.shared.b16 {%0,%1,%2,%3}, [%4];"
                 : "=r"(r[0]), "=r"(r[1]), "=r"(r[2]), "=r"(r[3]) : "r"(addr));
}
__device__ __forceinline__ void mma_f16(float* c, const uint32_t* a, uint32_t b0, uint32_t b1) {
    asm volatile("mma.sync.aligned.m16n8k16.row.col.f32.f16.f16.f32 "
                 "{%0,%1,%2,%3}, {%4,%5,%6,%7}, {%8,%9}, {%0,%1,%2,%3};"
                 : "+f"(c[0]), "+f"(c[1]), "+f"(c[2]), "+f"(c[3])
                 : "r"(a[0]), "r"(a[1]), "r"(a[2]), "r"(a[3]), "r"(b0), "r"(b1));
}

// ---------------- CSR construction ------------------------------------------
__global__ void k_zero_deg() {
    int i = blockIdx.x * blockDim.x + threadIdx.x;
    if (i < Rr * Nn) { g_deg_r[i] = 0; g_deg_c[i] = 0; }
}
__global__ void k_hist(const int* __restrict__ ei) {
    int idx = blockIdx.x * blockDim.x + threadIdx.x;
    if (idx >= Rr * Ee) return;
    int r = idx / Ee, e = idx - r * Ee;
    const int* base = ei + (size_t)r * 2 * Ee;
    atomicAdd(&g_deg_r[r * Nn + base[e]], 1);
    atomicAdd(&g_deg_c[r * Nn + base[Ee + e]], 1);
}
__global__ void k_dinv() {
    int i = blockIdx.x * blockDim.x + threadIdx.x;
    if (i >= Rr * Nn) return;
    g_dinv_r[i] = rsqrtf(fmaxf((float)g_deg_r[i], 1.0f));
    g_dinv_c[i] = rsqrtf(fmaxf((float)g_deg_c[i], 1.0f));
}

// ---- multi-block scan ---------------------------------------------------
__global__ __launch_bounds__(1024) void k_scan1() {
    int r = blockIdx.y, b = blockIdx.x;
    int t = threadIdx.x, lane = t & 31, w = t >> 5;
    __shared__ int wsum[32];
    int i0 = b * 4096 + t * 4;
    int v[4], s = 0;
#pragma unroll
    for (int j = 0; j < 4; j++) {
        v[j] = (i0 + j < Nn) ? g_deg_r[r * Nn + i0 + j] : 0;
        s += v[j];
    }
    int x = s;
#pragma unroll
    for (int o = 1; o < 32; o <<= 1) {
        int y = __shfl_up_sync(0xffffffffu, x, o);
        if (lane >= o) x += y;
    }
    if (lane == 31) wsum[w] = x;
    __syncthreads();
    if (w == 0) {
        int s2 = wsum[lane];
#pragma unroll
        for (int o = 1; o < 32; o <<= 1) {
            int y = __shfl_up_sync(0xffffffffu, s2, o);
            if (lane >= o) s2 += y;
        }
        wsum[lane] = s2;
    }
    __syncthreads();
    int woff = (w == 0) ? 0 : wsum[w - 1];
    int run = woff + x - s;
#pragma unroll
    for (int j = 0; j < 4; j++) {
        if (i0 + j < Nn) g_row_ptr[r * (Nn + 1) + i0 + j] = run;
        run += v[j];
    }
    if (t == 1023) g_blksum[r * NBLK + b] = woff + x;
}
__global__ void k_scan2() {
    int t = threadIdx.x, lane = t & 31, w = t >> 5;
    int v = (lane < NBLK) ? g_blksum[w * NBLK + lane] : 0;
    int x = v;
#pragma unroll
    for (int o = 1; o < 32; o <<= 1) {
        int y = __shfl_up_sync(0xffffffffu, x, o);
        if (lane >= o) x += y;
    }
    if (lane < NBLK) g_blksum[w * NBLK + lane] = x - v;
    if (lane == NBLK - 1) g_row_ptr[w * (Nn + 1) + Nn] = x;
}
__global__ __launch_bounds__(1024) void k_scan3() {
    int r = blockIdx.y, b = blockIdx.x;
    int off = g_blksum[r * NBLK + b];
    int i0 = b * 4096 + threadIdx.x * 4;
#pragma unroll
    for (int j = 0; j < 4; j++) {
        int i = i0 + j;
        if (i < Nn) {
            int p = g_row_ptr[r * (Nn + 1) + i] + off;
            g_row_ptr[r * (Nn + 1) + i] = p;
            g_cursor[r * Nn + i] = p;
        }
    }
}

__global__ void k_scatter(const int* __restrict__ ei) {
    int idx = blockIdx.x * blockDim.x + threadIdx.x;
    if (idx >= Rr * Ee) return;
    int r = idx / Ee, e = idx - r * Ee;
    const int* base = ei + (size_t)r * 2 * Ee;
    int row = base[e];
    int col = base[Ee + e];
    int pos = atomicAdd(&g_cursor[r * Nn + row], 1);
    float w = g_dinv_r[r * Nn + row] * g_dinv_c[r * Nn + col];
    g_edge[(size_t)r * Ee + pos] = make_int2(col, __float_as_int(w));
}

// ---------------- fp32 -> fp16 conversion ------------------------------------
__global__ void k_cvt(const float* __restrict__ x, __half* __restrict__ dst) {
    int idx = blockIdx.x * blockDim.x + threadIdx.x;
    const int total = Nn * Hh / 4;
    if (idx >= total) return;
    float4 v = ((const float4*)x)[idx];
    __half2 p0 = __floats2half2_rn(v.x, v.y);
    __half2 p1 = __floats2half2_rn(v.z, v.w);
    uint2 u;
    u.x = *(const uint32_t*)&p0;
    u.y = *(const uint32_t*)&p1;
    ((uint2*)dst)[idx] = u;
}

// ---------------- SpMM: warp per row, fp16 gather, 4-edge pipelined ---------
__device__ __forceinline__ void fma8(float* acc, float w, const uint4& v) {
    const __half2* h = (const __half2*)&v;
    float2 f;
    f = __half22float2(h[0]); acc[0] += w * f.x; acc[1] += w * f.y;
    f = __half22float2(h[1]); acc[2] += w * f.x; acc[3] += w * f.y;
    f = __half22float2(h[2]); acc[4] += w * f.x; acc[5] += w * f.y;
    f = __half22float2(h[3]); acc[6] += w * f.x; acc[7] += w * f.y;
}

__global__ __launch_bounds__(256) void k_spmm(int use_h1) {
    int r = blockIdx.y;
    int n = blockIdx.x * 8 + (threadIdx.x >> 5);
    if (n >= Nn) return;
    int lane = threadIdx.x & 31;
    const uint4* __restrict__ src = (const uint4*)(use_h1 ? g_h1h : g_Xh);
    int beg = g_row_ptr[r * (Nn + 1) + n];
    int end = g_row_ptr[r * (Nn + 1) + n + 1];
    const int2* __restrict__ edges = g_edge + (size_t)r * Ee;
    float acc[8];
#pragma unroll
    for (int j = 0; j < 8; j++) acc[j] = 0.f;

    int e = beg;
    for (; e + 4 <= end; e += 4) {
        int2 d0 = __ldg(edges + e);
        int2 d1 = __ldg(edges + e + 1);
        int2 d2 = __ldg(edges + e + 2);
        int2 d3 = __ldg(edges + e + 3);
        uint4 v0 = __ldg(src + ((size_t)d0.x << 5) + lane);
        uint4 v1 = __ldg(src + ((size_t)d1.x << 5) + lane);
        uint4 v2 = __ldg(src + ((size_t)d2.x << 5) + lane);
        uint4 v3 = __ldg(src + ((size_t)d3.x << 5) + lane);
        fma8(acc, __int_as_float(d0.y), v0);
        fma8(acc, __int_as_float(d1.y), v1);
        fma8(acc, __int_as_float(d2.y), v2);
        fma8(acc, __int_as_float(d3.y), v3);
    }
    for (; e < end; ++e) {
        int2 d = __ldg(edges + e);
        uint4 v = __ldg(src + ((size_t)d.x << 5) + lane);
        fma8(acc, __int_as_float(d.y), v);
    }

    __half2 p0 = __floats2half2_rn(acc[0], acc[1]);
    __half2 p1 = __floats2half2_rn(acc[2], acc[3]);
    __half2 p2 = __floats2half2_rn(acc[4], acc[5]);
    __half2 p3 = __floats2half2_rn(acc[6], acc[7]);
    uint4 o;
    o.x = *(const uint32_t*)&p0; o.y = *(const uint32_t*)&p1;
    o.z = *(const uint32_t*)&p2; o.w = *(const uint32_t*)&p3;
    g_S16[((size_t)r * Nn + n) * 32 + lane] = o;
}

// ---------------- W split+transpose: fp16 hi/lo, Bhi[r][n][k] ---------------
__global__ void k_splitW(const float* __restrict__ W) {
    int idx = blockIdx.x * blockDim.x + threadIdx.x;
    if (idx >= Rr * 256 * 256) return;
    int r = idx >> 16;
    int n = (idx >> 8) & 255;
    int k = idx & 255;
    float w = W[((size_t)r << 16) + ((size_t)k << 8) + n];
    __half hh = __float2half_rn(w);
    __half ll = __float2half_rn(w - __half2float(hh));
    size_t o = ((size_t)r << 16) + ((size_t)n << 8) + k;
    ((unsigned short*)g_Bhi)[o] = __half_as_ushort(hh);
    ((unsigned short*)g_Blo)[o] = __half_as_ushort(ll);
}

// ---------------- GEMM: H[r] = ReLU(S[r] @ W[r]), fp16 2-term ---------------
// A (fp16, exact) used directly; W = Whi + Wlo (fp16 split, 22-bit mantissa).
#define A_STRIDE 72
#define B_STRIDE 264
#define ASZ (128 * A_STRIDE * 2)            // 18432 B, one A stage
#define SM_B_HI 0
#define SM_B_LO (128 * B_STRIDE * 2)        // 67584
#define SM_A0   (2 * 128 * B_STRIDE * 2)    // 135168
#define SMEM_GEMM (SM_A0 + 2 * ASZ)         // 172032

__global__ __launch_bounds__(256) void k_gemm() {
    extern __shared__ char smem[];
    uint32_t sb = smem_to_u32(smem);
    int tid = threadIdx.x, lane = tid & 31, wid = tid >> 5;
    int wm = wid >> 1, wn = wid & 1;
    int r = blockIdx.z, m0 = blockIdx.x * 128, n0 = blockIdx.y * 128;

    // B loads (whole 128 x 256 hi+lo) via cp.async
    {
        const uint4* bh = g_Bhi + ((size_t)(r * 256 + n0)) * 32;
        const uint4* bl = g_Blo + ((size_t)(r * 256 + n0)) * 32;
#pragma unroll
        for (int j = 0; j < 16; j++) {
            int lin = tid + j * 256;
            int row = lin >> 5, ch = lin & 31;
            uint32_t so = row * (B_STRIDE * 2) + ch * 16;
            cp16(sb + SM_B_HI + so, bh + row * 32 + ch, 16);
            cp16(sb + SM_B_LO + so, bl + row * 32 + ch, 16);
        }
    }
    asm volatile("cp.async.commit_group;" ::: "memory");

    // A staging: LDG fp16 chunks into registers, STS directly (no split)
    uint4 stage[4];
    auto loadA = [&](int kc) {
#pragma unroll
        for (int j = 0; j < 4; j++) {
            int lin = tid + j * 256;
            int row = lin >> 3, ch = lin & 7;
            int gm = m0 + row;
            int gmc = (gm < Nn) ? gm : (Nn - 1);
            stage[j] = __ldg(g_S16 + ((size_t)r * Nn + gmc) * 32 + kc * 8 + ch);
        }
    };
    auto stsA = [&](int kc) {
        char* abase = smem + SM_A0 + (kc & 1) * ASZ;
#pragma unroll
        for (int j = 0; j < 4; j++) {
            int lin = tid + j * 256;
            int row = lin >> 3, ch = lin & 7;
            uint32_t so = row * (A_STRIDE * 2) + ch * 16;
            *(uint4*)(abase + so) = stage[j];
        }
    };

    loadA(0);

    float acc[2][8][4];
#pragma unroll
    for (int a = 0; a < 2; a++)
#pragma unroll
        for (int b = 0; b < 8; b++)
#pragma unroll
            for (int c = 0; c < 4; c++) acc[a][b][c] = 0.f;

    int krow = lane & 15;
    int kof  = (lane >> 4) * 8;

    for (int kc = 0; kc < 4; kc++) {
        stsA(kc);
        if (kc == 0) asm volatile("cp.async.wait_group 0;" ::: "memory");
        if (kc < 3) loadA(kc + 1);
        __syncthreads();

        uint32_t ab = sb + SM_A0 + (kc & 1) * ASZ;
#pragma unroll
        for (int kk = 0; kk < 4; kk++) {
            uint32_t afr[2][4], bhi[4][4], blo[4][4];
            uint32_t a_off = (wm * 32 + krow) * (A_STRIDE * 2) + (kk * 16 + kof) * 2;
            ldsm4(afr[0], ab + a_off);
            ldsm4(afr[1], ab + a_off + 16 * (A_STRIDE * 2));
            int kg = kc * 64 + kk * 16 + kof;
#pragma unroll
            for (int nq = 0; nq < 4; nq++) {
                uint32_t b_off = (wn * 64 + nq * 16 + krow) * (B_STRIDE * 2) + kg * 2;
                ldsm4(bhi[nq], sb + SM_B_HI + b_off);
                ldsm4(blo[nq], sb + SM_B_LO + b_off);
            }
#pragma unroll
            for (int mt = 0; mt < 2; mt++) {
#pragma unroll
                for (int nq = 0; nq < 4; nq++) {
                    float* cl = acc[mt][nq * 2];
                    float* ch = acc[mt][nq * 2 + 1];
                    mma_f16(cl, afr[mt], bhi[nq][0], bhi[nq][2]);
                    mma_f16(ch, afr[mt], bhi[nq][1], bhi[nq][3]);
                    mma_f16(cl, afr[mt], blo[nq][0], blo[nq][2]);
                    mma_f16(ch, afr[mt], blo[nq][1], blo[nq][3]);
                }
            }
        }
        __syncthreads();
    }

    int gm_base = m0 + wm * 32 + (lane >> 2);
    int gn_base = n0 + wn * 64 + (lane & 3) * 2;
#pragma unroll
    for (int mt = 0; mt < 2; mt++) {
#pragma unroll
        for (int nn = 0; nn < 8; nn++) {
            float* c = acc[mt][nn];
            int gm = gm_base + mt * 16;
            int gn = gn_base + nn * 8;
            if (gm < Nn) {
                float2 v = make_float2(fmaxf(c[0], 0.f), fmaxf(c[1], 0.f));
                *(float2*)(g_H + ((size_t)r * Nn + gm) * Hh + gn) = v;
            }
            if (gm + 8 < Nn) {
                float2 v = make_float2(fmaxf(c[2], 0.f), fmaxf(c[3], 0.f));
                *(float2*)(g_H + ((size_t)r * Nn + gm + 8) * Hh + gn) = v;
            }
        }
    }
}

// ---------------- layer-1 mean: h1 = 0.25 * sum_r H[r] -> fp16 --------------
__global__ void k_mean() {
    int idx = blockIdx.x * blockDim.x + threadIdx.x;
    const int total = Nn * Hh / 4;
    if (idx >= total) return;
    const float4* h = (const float4*)g_H;
    size_t off = (size_t)Nn * Hh / 4;
    float4 a = h[idx], b = h[idx + off], c = h[idx + 2 * off], d = h[idx + 3 * off];
    float4 m;
    m.x = 0.25f * (a.x + b.x + c.x + d.x);
    m.y = 0.25f * (a.y + b.y + c.y + d.y);
    m.z = 0.25f * (a.z + b.z + c.z + d.z);
    m.w = 0.25f * (a.w + b.w + c.w + d.w);
    __half2 p0 = __floats2half2_rn(m.x, m.y);
    __half2 p1 = __floats2half2_rn(m.z, m.w);
    uint2 u;
    u.x = *(const uint32_t*)&p0;
    u.y = *(const uint32_t*)&p1;
    ((uint2*)g_h1h)[idx] = u;
}

// ---------------- attention + residual fusion + output GEMM -----------------
__global__ __launch_bounds__(256) void k_attn(const float* __restrict__ att_q,
                                              const float* __restrict__ tau_p,
                                              const float* __restrict__ W_out,
                                              const float* __restrict__ b_out,
                                              float* __restrict__ out) {
    int n = blockIdx.x * 8 + (threadIdx.x >> 5);
    if (n >= Nn) return;
    int lane = threadIdx.x & 31;

    float q[8];
#pragma unroll
    for (int k = 0; k < 8; k++) q[k] = att_q[lane + 32 * k];

    float v[4][8];
    float sc[4];
#pragma unroll
    for (int r = 0; r < 4; r++) {
        const float* h = g_H + ((size_t)r * Nn + n) * Hh;
        float s = 0.f;
#pragma unroll
        for (int k = 0; k < 8; k++) {
            v[r][k] = h[lane + 32 * k];
            s += v[r][k] * q[k];
        }
#pragma unroll
        for (int o = 16; o; o >>= 1) s += __shfl_xor_sync(0xffffffffu, s, o);
        sc[r] = s;
    }
    float tc = fminf(fmaxf(tau_p[0], 0.5f), 5.0f);
    float inv = 1.0f / tc;
    float s0 = sc[0] * inv, s1 = sc[1] * inv, s2 = sc[2] * inv, s3 = sc[3] * inv;
    float m = fmaxf(fmaxf(s0, s1), fmaxf(s2, s3));
    float e0 = expf(s0 - m), e1 = expf(s1 - m), e2 = expf(s2 - m), e3 = expf(s3 - m);
    float se = e0 + e1 + e2 + e3;
    float al[4] = {e0 / se, e1 / se, e2 / se, e3 / se};

    float h2[8];
#pragma unroll
    for (int k = 0; k < 8; k++)
        h2[k] = (0.25f + al[0]) * v[0][k] + (0.25f + al[1]) * v[1][k] +
                (0.25f + al[2]) * v[2][k] + (0.25f + al[3]) * v[3][k];

    float acc[16];
#pragma unroll
    for (int c = 0; c < 16; c++) acc[c] = 0.f;
#pragma unroll
    for (int k = 0; k < 8; k++) {
        int idx = lane + 32 * k;
        const float4* wr = (const float4*)(W_out + (size_t)idx * 16);
        float4 w0 = wr[0], w1 = wr[1], w2 = wr[2], w3 = wr[3];
        float hv = h2[k];
        acc[0]  += hv * w0.x; acc[1]  += hv * w0.y; acc[2]  += hv * w0.z; acc[3]  += hv * w0.w;
        acc[4]  += hv * w1.x; acc[5]  += hv * w1.y; acc[6]  += hv * w1.z; acc[7]  += hv * w1.w;
        acc[8]  += hv * w2.x; acc[9]  += hv * w2.y; acc[10] += hv * w2.z; acc[11] += hv * w2.w;
        acc[12] += hv * w3.x; acc[13] += hv * w3.y; acc[14] += hv * w3.z; acc[15] += hv * w3.w;
    }
#pragma unroll
    for (int c = 0; c < 16; c++)
#pragma unroll
        for (int o = 16; o; o >>= 1) acc[c] += __shfl_xor_sync(0xffffffffu, acc[c], o);

    if (lane < 16) {
        float lg = 0.f;
#pragma unroll
        for (int c = 0; c < 16; c++)
            if (lane == c) lg = acc[c];
        out[(size_t)n * Cc + lane] = lg + b_out[lane];
    }
    if (lane < 4) {
        float a = al[0];
        if (lane == 1) a = al[1];
        if (lane == 2) a = al[2];
        if (lane == 3) a = al[3];
        out[(size_t)Nn * Cc + (size_t)n * Rr + lane] = a;
    }
}

// ---------------- launch (serial — overlap proven counterproductive) --------
extern "C" void kernel_launch(void* const* d_in, const int* in_sizes, int n_in,
                              void* d_out, int out_size) {
    const float* X     = (const float*)d_in[0];
    const int*   EI    = (const int*)d_in[1];
    const float* W1    = (const float*)d_in[2];
    const float* W2    = (const float*)d_in[3];
    const float* att_q = (const float*)d_in[4];
    const float* tau   = (const float*)d_in[5];
    const float* W_out = (const float*)d_in[6];
    const float* b_out = (const float*)d_in[7];
    float* out = (float*)d_out;
    (void)in_sizes; (void)n_in; (void)out_size;

    cudaFuncSetAttribute(k_gemm, cudaFuncAttributeMaxDynamicSharedMemorySize, SMEM_GEMM);

    // CSR build
    k_zero_deg<<<(Rr * Nn + 255) / 256, 256>>>();
    k_hist<<<(Rr * Ee + 255) / 256, 256>>>(EI);
    k_dinv<<<(Rr * Nn + 255) / 256, 256>>>();
    k_scan1<<<dim3(NBLK, Rr), 1024>>>();
    k_scan2<<<1, 128>>>();
    k_scan3<<<dim3(NBLK, Rr), 1024>>>();
    k_scatter<<<(Rr * Ee + 255) / 256, 256>>>(EI);

    // fp16 copy of X for gathers
    __half* xh;
    cudaGetSymbolAddress((void**)&xh, g_Xh);
    k_cvt<<<(Nn * Hh / 4 + 255) / 256, 256>>>(X, xh);

    dim3 spmm_grid((Nn + 7) / 8, Rr);
    dim3 gemm_grid((Nn + 127) / 128, Hh / 128, Rr);

    // Layer 1
    k_spmm<<<spmm_grid, 256>>>(0);
    k_splitW<<<(Rr * 256 * 256 + 255) / 256, 256>>>(W1);
    k_gemm<<<gemm_grid, 256, SMEM_GEMM>>>();
    k_mean<<<(Nn * Hh / 4 + 255) / 256, 256>>>();

    // Layer 2
    k_spmm<<<spmm_grid, 256>>>(1);
    k_splitW<<<(Rr * 256 * 256 + 255) / 256, 256>>>(W2);
    k_gemm<<<gemm_grid, 256, SMEM_GEMM>>>();

    // Attention + output head
    k_attn<<<(Nn + 7) / 8, 256>>>(att_q, tau, W_out, b_out, out);
}

// round 14
// speedup vs baseline: 1.2845x; 1.0384x over previous
#include <cuda_runtime.h>
#include <cuda_bf16.h>
#include <cuda_fp16.h>
#include <cstdint>
#include <math.h>

#define Nn 50000
#define Rr 4
#define Ee 1600000
#define Hh 256
#define Cc 16
#define NBLK 13   // ceil(50000 / 4096)

// ---------------- scratch (device globals; no runtime allocation) ----------
__device__ int   g_deg_r[Rr * Nn];
__device__ int   g_deg_c[Rr * Nn];
__device__ float g_dinv_r[Rr * Nn];
__device__ float g_dinv_c[Rr * Nn];
__device__ int   g_row_ptr[Rr * (Nn + 1)];
__device__ int   g_cursor[Rr * Nn];
__device__ int   g_blksum[Rr * NBLK];
__device__ int2  g_edge[(size_t)Rr * Ee];   // packed {col, wgt_bits}
// fp16 gather sources
__device__ __half g_Xh[(size_t)Nn * Hh];
__device__ __half g_h1h[(size_t)Nn * Hh];
// SpMM outputs packed fp16: [R][N][256] fp16 = 32 uint4 per row
__device__ uint4 g_S16[(size_t)Rr * Nn * 32];
// fp16 hi/lo split of W transposed to n-major: [R][n=256][k=256]
__device__ uint4 g_Bhi[Rr * 256 * 32];
__device__ uint4 g_Blo[Rr * 256 * 32];
// per-relation hidden states, fp16 (coalesced-stored by GEMM epilogue)
__device__ __half g_Hh[(size_t)Rr * Nn * Hh];

// ---------------- low-level helpers (all base-arch PTX) ---------------------
__device__ __forceinline__ uint32_t smem_to_u32(const void* p) {
    uint32_t a;
    asm("{ .reg .u64 t; cvta.to.shared.u64 t, %1; cvt.u32.u64 %0, t; }" : "=r"(a) : "l"(p));
    return a;
}
__device__ __forceinline__ void cp16(uint32_t dst, const void* src, int sz) {
    asm volatile("cp.async.cg.shared.global [%0], [%1], 16, %2;"
                 :: "r"(dst), "l"(src), "r"(sz));
}
__device__ __forceinline__ void ldsm4(uint32_t* r, uint32_t addr) {
    asm volatile("ldmatrix.sync.aligned.m8n8.x4.shared.b16 {%0,%1,%2,%3}, [%4];"
                 : "=r"(r[0]), "=r"(r[1]), "=r"(r[2]), "=r"(r[3]) : "r"(addr));
}
__device__ __forceinline__ void mma_f16(float* c, const uint32_t* a, uint32_t b0, uint32_t b1) {
    asm volatile("mma.sync.aligned.m16n8k16.row.col.f32.f16.f16.f32 "
                 "{%0,%1,%2,%3}, {%4,%5,%6,%7}, {%8,%9}, {%0,%1,%2,%3};"
                 : "+f"(c[0]), "+f"(c[1]), "+f"(c[2]), "+f"(c[3])
                 : "r"(a[0]), "r"(a[1]), "r"(a[2]), "r"(a[3]), "r"(b0), "r"(b1));
}

// ---------------- CSR construction ------------------------------------------
__global__ void k_zero_deg() {
    int i = blockIdx.x * blockDim.x + threadIdx.x;
    if (i < Rr * Nn) { g_deg_r[i] = 0; g_deg_c[i] = 0; }
}
__global__ void k_hist(const int* __restrict__ ei) {
    int idx = blockIdx.x * blockDim.x + threadIdx.x;
    if (idx >= Rr * Ee) return;
    int r = idx / Ee, e = idx - r * Ee;
    const int* base = ei + (size_t)r * 2 * Ee;
    atomicAdd(&g_deg_r[r * Nn + base[e]], 1);
    atomicAdd(&g_deg_c[r * Nn + base[Ee + e]], 1);
}
__global__ void k_dinv() {
    int i = blockIdx.x * blockDim.x + threadIdx.x;
    if (i >= Rr * Nn) return;
    g_dinv_r[i] = rsqrtf(fmaxf((float)g_deg_r[i], 1.0f));
    g_dinv_c[i] = rsqrtf(fmaxf((float)g_deg_c[i], 1.0f));
}

// ---- multi-block scan ---------------------------------------------------
__global__ __launch_bounds__(1024) void k_scan1() {
    int r = blockIdx.y, b = blockIdx.x;
    int t = threadIdx.x, lane = t & 31, w = t >> 5;
    __shared__ int wsum[32];
    int i0 = b * 4096 + t * 4;
    int v[4], s = 0;
#pragma unroll
    for (int j = 0; j < 4; j++) {
        v[j] = (i0 + j < Nn) ? g_deg_r[r * Nn + i0 + j] : 0;
        s += v[j];
    }
    int x = s;
#pragma unroll
    for (int o = 1; o < 32; o <<= 1) {
        int y = __shfl_up_sync(0xffffffffu, x, o);
        if (lane >= o) x += y;
    }
    if (lane == 31) wsum[w] = x;
    __syncthreads();
    if (w == 0) {
        int s2 = wsum[lane];
#pragma unroll
        for (int o = 1; o < 32; o <<= 1) {
            int y = __shfl_up_sync(0xffffffffu, s2, o);
            if (lane >= o) s2 += y;
        }
        wsum[lane] = s2;
    }
    __syncthreads();
    int woff = (w == 0) ? 0 : wsum[w - 1];
    int run = woff + x - s;
#pragma unroll
    for (int j = 0; j < 4; j++) {
        if (i0 + j < Nn) g_row_ptr[r * (Nn + 1) + i0 + j] = run;
        run += v[j];
    }
    if (t == 1023) g_blksum[r * NBLK + b] = woff + x;
}
__global__ void k_scan2() {
    int t = threadIdx.x, lane = t & 31, w = t >> 5;
    int v = (lane < NBLK) ? g_blksum[w * NBLK + lane] : 0;
    int x = v;
#pragma unroll
    for (int o = 1; o < 32; o <<= 1) {
        int y = __shfl_up_sync(0xffffffffu, x, o);
        if (lane >= o) x += y;
    }
    if (lane < NBLK) g_blksum[w * NBLK + lane] = x - v;
    if (lane == NBLK - 1) g_row_ptr[w * (Nn + 1) + Nn] = x;
}
__global__ __launch_bounds__(1024) void k_scan3() {
    int r = blockIdx.y, b = blockIdx.x;
    int off = g_blksum[r * NBLK + b];
    int i0 = b * 4096 + threadIdx.x * 4;
#pragma unroll
    for (int j = 0; j < 4; j++) {
        int i = i0 + j;
        if (i < Nn) {
            int p = g_row_ptr[r * (Nn + 1) + i] + off;
            g_row_ptr[r * (Nn + 1) + i] = p;
            g_cursor[r * Nn + i] = p;
        }
    }
}

__global__ void k_scatter(const int* __restrict__ ei) {
    int idx = blockIdx.x * blockDim.x + threadIdx.x;
    if (idx >= Rr * Ee) return;
    int r = idx / Ee, e = idx - r * Ee;
    const int* base = ei + (size_t)r * 2 * Ee;
    int row = base[e];
    int col = base[Ee + e];
    int pos = atomicAdd(&g_cursor[r * Nn + row], 1);
    float w = g_dinv_r[r * Nn + row] * g_dinv_c[r * Nn + col];
    g_edge[(size_t)r * Ee + pos] = make_int2(col, __float_as_int(w));
}

// ---------------- fp32 -> fp16 conversion ------------------------------------
__global__ void k_cvt(const float* __restrict__ x, __half* __restrict__ dst) {
    int idx = blockIdx.x * blockDim.x + threadIdx.x;
    const int total = Nn * Hh / 4;
    if (idx >= total) return;
    float4 v = ((const float4*)x)[idx];
    __half2 p0 = __floats2half2_rn(v.x, v.y);
    __half2 p1 = __floats2half2_rn(v.z, v.w);
    uint2 u;
    u.x = *(const uint32_t*)&p0;
    u.y = *(const uint32_t*)&p1;
    ((uint2*)dst)[idx] = u;
}

// ---------------- SpMM: warp per row, fp16 gather, 4-edge pipelined ---------
__device__ __forceinline__ void fma8(float* acc, float w, const uint4& v) {
    const __half2* h = (const __half2*)&v;
    float2 f;
    f = __half22float2(h[0]); acc[0] += w * f.x; acc[1] += w * f.y;
    f = __half22float2(h[1]); acc[2] += w * f.x; acc[3] += w * f.y;
    f = __half22float2(h[2]); acc[4] += w * f.x; acc[5] += w * f.y;
    f = __half22float2(h[3]); acc[6] += w * f.x; acc[7] += w * f.y;
}

__global__ __launch_bounds__(256) void k_spmm(int use_h1) {
    int r = blockIdx.y;
    int n = blockIdx.x * 8 + (threadIdx.x >> 5);
    if (n >= Nn) return;
    int lane = threadIdx.x & 31;
    const uint4* __restrict__ src = (const uint4*)(use_h1 ? g_h1h : g_Xh);
    int beg = g_row_ptr[r * (Nn + 1) + n];
    int end = g_row_ptr[r * (Nn + 1) + n + 1];
    const int2* __restrict__ edges = g_edge + (size_t)r * Ee;
    float acc[8];
#pragma unroll
    for (int j = 0; j < 8; j++) acc[j] = 0.f;

    int e = beg;
    for (; e + 4 <= end; e += 4) {
        int2 d0 = __ldg(edges + e);
        int2 d1 = __ldg(edges + e + 1);
        int2 d2 = __ldg(edges + e + 2);
        int2 d3 = __ldg(edges + e + 3);
        uint4 v0 = __ldg(src + ((size_t)d0.x << 5) + lane);
        uint4 v1 = __ldg(src + ((size_t)d1.x << 5) + lane);
        uint4 v2 = __ldg(src + ((size_t)d2.x << 5) + lane);
        uint4 v3 = __ldg(src + ((size_t)d3.x << 5) + lane);
        fma8(acc, __int_as_float(d0.y), v0);
        fma8(acc, __int_as_float(d1.y), v1);
        fma8(acc, __int_as_float(d2.y), v2);
        fma8(acc, __int_as_float(d3.y), v3);
    }
    for (; e < end; ++e) {
        int2 d = __ldg(edges + e);
        uint4 v = __ldg(src + ((size_t)d.x << 5) + lane);
        fma8(acc, __int_as_float(d.y), v);
    }

    __half2 p0 = __floats2half2_rn(acc[0], acc[1]);
    __half2 p1 = __floats2half2_rn(acc[2], acc[3]);
    __half2 p2 = __floats2half2_rn(acc[4], acc[5]);
    __half2 p3 = __floats2half2_rn(acc[6], acc[7]);
    uint4 o;
    o.x = *(const uint32_t*)&p0; o.y = *(const uint32_t*)&p1;
    o.z = *(const uint32_t*)&p2; o.w = *(const uint32_t*)&p3;
    g_S16[((size_t)r * Nn + n) * 32 + lane] = o;
}

// ---------------- W split+transpose: fp16 hi/lo, Bhi[r][n][k] ---------------
__global__ void k_splitW(const float* __restrict__ W) {
    int idx = blockIdx.x * blockDim.x + threadIdx.x;
    if (idx >= Rr * 256 * 256) return;
    int r = idx >> 16;
    int n = (idx >> 8) & 255;
    int k = idx & 255;
    float w = W[((size_t)r << 16) + ((size_t)k << 8) + n];
    __half hh = __float2half_rn(w);
    __half ll = __float2half_rn(w - __half2float(hh));
    size_t o = ((size_t)r << 16) + ((size_t)n << 8) + k;
    ((unsigned short*)g_Bhi)[o] = __half_as_ushort(hh);
    ((unsigned short*)g_Blo)[o] = __half_as_ushort(ll);
}

// ---------------- GEMM: Hh[r] = ReLU(S[r] @ W[r]), fp16 2-term --------------
// K-chunked (64) double-buffered A+Bhi+Blo via cp.async; 110.6KB smem -> 2 CTA/SM.
// Epilogue: stage fp16 tile in smem, coalesced 16B stores to g_Hh.
#define CH_STRIDE 72                       // halfs per row (64 + 8 pad)
#define CHSZ (128 * CH_STRIDE * 2)         // 18432 B per chunk part
#define STG  (3 * CHSZ)                    // A + Bhi + Blo per stage = 55296
#define SMEM_GEMM (2 * STG)                // 110592
#define EP_STRIDE 136                      // epilogue halfs per row (128 + 8 pad)

__global__ __launch_bounds__(256) void k_gemm() {
    extern __shared__ char smem[];
    uint32_t sb = smem_to_u32(smem);
    int tid = threadIdx.x, lane = tid & 31, wid = tid >> 5;
    int wm = wid >> 1, wn = wid & 1;
    int r = blockIdx.z, m0 = blockIdx.x * 128, n0 = blockIdx.y * 128;

    auto issue = [&](int kc) {
        uint32_t base = sb + (kc & 1) * STG;
        const uint4* bh = g_Bhi + ((size_t)(r * 256 + n0)) * 32 + kc * 8;
        const uint4* bl = g_Blo + ((size_t)(r * 256 + n0)) * 32 + kc * 8;
#pragma unroll
        for (int j = 0; j < 4; j++) {
            int lin = tid + j * 256;
            int row = lin >> 3, ch = lin & 7;
            uint32_t so = row * (CH_STRIDE * 2) + ch * 16;
            int gm = m0 + row;
            int sz = (gm < Nn) ? 16 : 0;
            int gmc = (gm < Nn) ? gm : (Nn - 1);
            cp16(base + so, g_S16 + ((size_t)r * Nn + gmc) * 32 + kc * 8 + ch, sz);
            cp16(base + CHSZ + so, bh + row * 32 + ch, 16);
            cp16(base + 2 * CHSZ + so, bl + row * 32 + ch, 16);
        }
    };

    issue(0);
    asm volatile("cp.async.commit_group;" ::: "memory");

    float acc[2][8][4];
#pragma unroll
    for (int a = 0; a < 2; a++)
#pragma unroll
        for (int b = 0; b < 8; b++)
#pragma unroll
            for (int c = 0; c < 4; c++) acc[a][b][c] = 0.f;

    int krow = lane & 15;
    int kof  = (lane >> 4) * 8;

    for (int kc = 0; kc < 4; kc++) {
        if (kc < 3) {
            issue(kc + 1);
            asm volatile("cp.async.commit_group;" ::: "memory");
            asm volatile("cp.async.wait_group 1;" ::: "memory");
        } else {
            asm volatile("cp.async.wait_group 0;" ::: "memory");
        }
        __syncthreads();

        uint32_t ab  = sb + (kc & 1) * STG;
        uint32_t bhB = ab + CHSZ;
        uint32_t blB = ab + 2 * CHSZ;
#pragma unroll
        for (int kk = 0; kk < 4; kk++) {
            uint32_t afr[2][4], bhi[4][4], blo[4][4];
            uint32_t a_off = (wm * 32 + krow) * (CH_STRIDE * 2) + (kk * 16 + kof) * 2;
            ldsm4(afr[0], ab + a_off);
            ldsm4(afr[1], ab + a_off + 16 * (CH_STRIDE * 2));
#pragma unroll
            for (int nq = 0; nq < 4; nq++) {
                uint32_t b_off = (wn * 64 + nq * 16 + krow) * (CH_STRIDE * 2) + (kk * 16 + kof) * 2;
                ldsm4(bhi[nq], bhB + b_off);
                ldsm4(blo[nq], blB + b_off);
            }
#pragma unroll
            for (int mt = 0; mt < 2; mt++) {
#pragma unroll
                for (int nq = 0; nq < 4; nq++) {
                    float* cl = acc[mt][nq * 2];
                    float* ch = acc[mt][nq * 2 + 1];
                    mma_f16(cl, afr[mt], bhi[nq][0], bhi[nq][2]);
                    mma_f16(ch, afr[mt], bhi[nq][1], bhi[nq][3]);
                    mma_f16(cl, afr[mt], blo[nq][0], blo[nq][2]);
                    mma_f16(ch, afr[mt], blo[nq][1], blo[nq][3]);
                }
            }
        }
        __syncthreads();
    }

    // ---- epilogue: pack fp16 tile in smem, then coalesced stores ----------
    int rbase = wm * 32 + (lane >> 2);
    int cbase = wn * 64 + (lane & 3) * 2;
#pragma unroll
    for (int mt = 0; mt < 2; mt++) {
#pragma unroll
        for (int nn = 0; nn < 8; nn++) {
            float* c = acc[mt][nn];
            int row = rbase + mt * 16;
            int col = cbase + nn * 8;
            __half2 v01 = __floats2half2_rn(fmaxf(c[0], 0.f), fmaxf(c[1], 0.f));
            __half2 v23 = __floats2half2_rn(fmaxf(c[2], 0.f), fmaxf(c[3], 0.f));
            *(__half2*)(smem + (size_t)row * (EP_STRIDE * 2) + col * 2) = v01;
            *(__half2*)(smem + (size_t)(row + 8) * (EP_STRIDE * 2) + col * 2) = v23;
        }
    }
    __syncthreads();
#pragma unroll
    for (int j = 0; j < 8; j++) {
        int lin = tid + j * 256;
        int row = lin >> 4, ch = lin & 15;
        int gm = m0 + row;
        if (gm < Nn) {
            uint4 v = *(const uint4*)(smem + (size_t)row * (EP_STRIDE * 2) + ch * 16);
            *(uint4*)(g_Hh + ((size_t)r * Nn + gm) * Hh + n0 + ch * 8) = v;
        }
    }
}

// ---------------- layer-1 mean: h1 = 0.25 * sum_r Hh[r] (fp16 in/out) -------
__global__ void k_mean() {
    int idx = blockIdx.x * blockDim.x + threadIdx.x;
    const int total = Nn * Hh / 8;   // 8 halfs per uint4
    if (idx >= total) return;
    const uint4* h = (const uint4*)g_Hh;
    size_t off = (size_t)Nn * Hh / 8;
    uint4 a = h[idx], b = h[idx + off], c = h[idx + 2 * off], d = h[idx + 3 * off];
    const __half2* a2 = (const __half2*)&a;
    const __half2* b2 = (const __half2*)&b;
    const __half2* c2 = (const __half2*)&c;
    const __half2* d2 = (const __half2*)&d;
    uint4 o;
    __half2* o2 = (__half2*)&o;
#pragma unroll
    for (int j = 0; j < 4; j++) {
        float2 fa = __half22float2(a2[j]), fb = __half22float2(b2[j]);
        float2 fc = __half22float2(c2[j]), fd = __half22float2(d2[j]);
        o2[j] = __floats2half2_rn(0.25f * (fa.x + fb.x + fc.x + fd.x),
                                  0.25f * (fa.y + fb.y + fc.y + fd.y));
    }
    ((uint4*)g_h1h)[idx] = o;
}

// ---------------- attention + residual fusion + output GEMM -----------------
__global__ __launch_bounds__(256) void k_attn(const float* __restrict__ att_q,
                                              const float* __restrict__ tau_p,
                                              const float* __restrict__ W_out,
                                              const float* __restrict__ b_out,
                                              float* __restrict__ out) {
    int n = blockIdx.x * 8 + (threadIdx.x >> 5);
    if (n >= Nn) return;
    int lane = threadIdx.x & 31;

    float2 q2[4];
#pragma unroll
    for (int j = 0; j < 4; j++) {
        int c = 2 * lane + 64 * j;
        q2[j] = make_float2(att_q[c], att_q[c + 1]);
    }

    float v[4][8];
    float sc[4];
#pragma unroll
    for (int r = 0; r < 4; r++) {
        const __half2* h = (const __half2*)(g_Hh + ((size_t)r * Nn + n) * Hh);
        float s = 0.f;
#pragma unroll
        for (int j = 0; j < 4; j++) {
            float2 f = __half22float2(h[lane + 32 * j]);
            v[r][2 * j] = f.x; v[r][2 * j + 1] = f.y;
            s += f.x * q2[j].x + f.y * q2[j].y;
        }
#pragma unroll
        for (int o = 16; o; o >>= 1) s += __shfl_xor_sync(0xffffffffu, s, o);
        sc[r] = s;
    }
    float tc = fminf(fmaxf(tau_p[0], 0.5f), 5.0f);
    float inv = 1.0f / tc;
    float s0 = sc[0] * inv, s1 = sc[1] * inv, s2 = sc[2] * inv, s3 = sc[3] * inv;
    float m = fmaxf(fmaxf(s0, s1), fmaxf(s2, s3));
    float e0 = expf(s0 - m), e1 = expf(s1 - m), e2 = expf(s2 - m), e3 = expf(s3 - m);
    float se = e0 + e1 + e2 + e3;
    float al[4] = {e0 / se, e1 / se, e2 / se, e3 / se};

    float h2[8];
#pragma unroll
    for (int k = 0; k < 8; k++)
        h2[k] = (0.25f + al[0]) * v[0][k] + (0.25f + al[1]) * v[1][k] +
                (0.25f + al[2]) * v[2][k] + (0.25f + al[3]) * v[3][k];

    float acc[16];
#pragma unroll
    for (int c = 0; c < 16; c++) acc[c] = 0.f;
#pragma unroll
    for (int j = 0; j < 4; j++) {
#pragma unroll
        for (int t = 0; t < 2; t++) {
            int idx = 2 * lane + 64 * j + t;
            const float4* wr = (const float4*)(W_out + (size_t)idx * 16);
            float4 w0 = wr[0], w1 = wr[1], w2 = wr[2], w3 = wr[3];
            float hv = h2[2 * j + t];
            acc[0]  += hv * w0.x; acc[1]  += hv * w0.y; acc[2]  += hv * w0.z; acc[3]  += hv * w0.w;
            acc[4]  += hv * w1.x; acc[5]  += hv * w1.y; acc[6]  += hv * w1.z; acc[7]  += hv * w1.w;
            acc[8]  += hv * w2.x; acc[9]  += hv * w2.y; acc[10] += hv * w2.z; acc[11] += hv * w2.w;
            acc[12] += hv * w3.x; acc[13] += hv * w3.y; acc[14] += hv * w3.z; acc[15] += hv * w3.w;
        }
    }
#pragma unroll
    for (int c = 0; c < 16; c++)
#pragma unroll
        for (int o = 16; o; o >>= 1) acc[c] += __shfl_xor_sync(0xffffffffu, acc[c], o);

    if (lane < 16) {
        float lg = 0.f;
#pragma unroll
        for (int c = 0; c < 16; c++)
            if (lane == c) lg = acc[c];
        out[(size_t)n * Cc + lane] = lg + b_out[lane];
    }
    if (lane < 4) {
        float a = al[0];
        if (lane == 1) a = al[1];
        if (lane == 2) a = al[2];
        if (lane == 3) a = al[3];
        out[(size_t)Nn * Cc + (size_t)n * Rr + lane] = a;
    }
}

// ---------------- launch (serial) --------------------------------------------
extern "C" void kernel_launch(void* const* d_in, const int* in_sizes, int n_in,
                              void* d_out, int out_size) {
    const float* X     = (const float*)d_in[0];
    const int*   EI    = (const int*)d_in[1];
    const float* W1    = (const float*)d_in[2];
    const float* W2    = (const float*)d_in[3];
    const float* att_q = (const float*)d_in[4];
    const float* tau   = (const float*)d_in[5];
    const float* W_out = (const float*)d_in[6];
    const float* b_out = (const float*)d_in[7];
    float* out = (float*)d_out;
    (void)in_sizes; (void)n_in; (void)out_size;

    cudaFuncSetAttribute(k_gemm, cudaFuncAttributeMaxDynamicSharedMemorySize, SMEM_GEMM);

    // CSR build
    k_zero_deg<<<(Rr * Nn + 255) / 256, 256>>>();
    k_hist<<<(Rr * Ee + 255) / 256, 256>>>(EI);
    k_dinv<<<(Rr * Nn + 255) / 256, 256>>>();
    k_scan1<<<dim3(NBLK, Rr), 1024>>>();
    k_scan2<<<1, 128>>>();
    k_scan3<<<dim3(NBLK, Rr), 1024>>>();
    k_scatter<<<(Rr * Ee + 255) / 256, 256>>>(EI);

    // fp16 copy of X for gathers
    __half* xh;
    cudaGetSymbolAddress((void**)&xh, g_Xh);
    k_cvt<<<(Nn * Hh / 4 + 255) / 256, 256>>>(X, xh);

    dim3 spmm_grid((Nn + 7) / 8, Rr);
    dim3 gemm_grid((Nn + 127) / 128, Hh / 128, Rr);

    // Layer 1
    k_spmm<<<spmm_grid, 256>>>(0);
    k_splitW<<<(Rr * 256 * 256 + 255) / 256, 256>>>(W1);
    k_gemm<<<gemm_grid, 256, SMEM_GEMM>>>();
    k_mean<<<(Nn * Hh / 8 + 255) / 256, 256>>>();

    // Layer 2
    k_spmm<<<spmm_grid, 256>>>(1);
    k_splitW<<<(Rr * 256 * 256 + 255) / 256, 256>>>(W2);
    k_gemm<<<gemm_grid, 256, SMEM_GEMM>>>();

    // Attention + output head
    k_attn<<<(Nn + 7) / 8, 256>>>(att_q, tau, W_out, b_out, out);
}

// round 15
// speedup vs baseline: 1.4019x; 1.0914x over previous
#include <cuda_runtime.h>
#include <cuda_bf16.h>
#include <cuda_fp16.h>
#include <cstdint>
#include <math.h>

#define Nn 50000
#define Rr 4
#define Ee 1600000
#define Hh 256
#define Cc 16
#define NBLK 13   // ceil(50000 / 4096)

// ---------------- scratch (device globals; no runtime allocation) ----------
__device__ int   g_deg_r[Rr * Nn];
__device__ int   g_deg_c[Rr * Nn];
__device__ int   g_row_ptr[Rr * (Nn + 1)];
__device__ int   g_cursor[Rr * Nn];
__device__ int   g_blksum[Rr * NBLK];
__device__ int2  g_edge[(size_t)Rr * Ee];   // packed {col, wgt_bits}
// fp16 gather sources
__device__ __half g_Xh[(size_t)Nn * Hh];
__device__ __half g_h1h[(size_t)Nn * Hh];
// SpMM outputs packed fp16: [R][N][256] fp16 = 32 uint4 per row
__device__ uint4 g_S16[(size_t)Rr * Nn * 32];
// fp16 W transposed to n-major: [R][n=256][k=256]
__device__ uint4 g_B16[Rr * 256 * 32];
// per-relation hidden states, fp16 (coalesced-stored by GEMM epilogue)
__device__ __half g_Hh[(size_t)Rr * Nn * Hh];

// ---------------- low-level helpers (all base-arch PTX) ---------------------
__device__ __forceinline__ uint32_t smem_to_u32(const void* p) {
    uint32_t a;
    asm("{ .reg .u64 t; cvta.to.shared.u64 t, %1; cvt.u32.u64 %0, t; }" : "=r"(a) : "l"(p));
    return a;
}
__device__ __forceinline__ void cp16(uint32_t dst, const void* src, int sz) {
    asm volatile("cp.async.cg.shared.global [%0], [%1], 16, %2;"
                 :: "r"(dst), "l"(src), "r"(sz));
}
__device__ __forceinline__ void ldsm4(uint32_t* r, uint32_t addr) {
    asm volatile("ldmatrix.sync.aligned.m8n8.x4.shared.b16 {%0,%1,%2,%3}, [%4];"
                 : "=r"(r[0]), "=r"(r[1]), "=r"(r[2]), "=r"(r[3]) : "r"(addr));
}
__device__ __forceinline__ void mma_f16(float* c, const uint32_t* a, uint32_t b0, uint32_t b1) {
    asm volatile("mma.sync.aligned.m16n8k16.row.col.f32.f16.f16.f32 "
                 "{%0,%1,%2,%3}, {%4,%5,%6,%7}, {%8,%9}, {%0,%1,%2,%3};"
                 : "+f"(c[0]), "+f"(c[1]), "+f"(c[2]), "+f"(c[3])
                 : "r"(a[0]), "r"(a[1]), "r"(a[2]), "r"(a[3]), "r"(b0), "r"(b1));
}

// ---------------- CSR construction ------------------------------------------
__global__ void k_zero_deg() {
    int i = blockIdx.x * blockDim.x + threadIdx.x;
    if (i < Rr * Nn) { g_deg_r[i] = 0; g_deg_c[i] = 0; }
}
__global__ void k_hist(const int* __restrict__ ei) {
    int idx = blockIdx.x * blockDim.x + threadIdx.x;
    if (idx >= Rr * Ee) return;
    int r = idx / Ee, e = idx - r * Ee;
    const int* base = ei + (size_t)r * 2 * Ee;
    atomicAdd(&g_deg_r[r * Nn + base[e]], 1);
    atomicAdd(&g_deg_c[r * Nn + base[Ee + e]], 1);
}

// ---- multi-block scan ---------------------------------------------------
__global__ __launch_bounds__(1024) void k_scan1() {
    int r = blockIdx.y, b = blockIdx.x;
    int t = threadIdx.x, lane = t & 31, w = t >> 5;
    __shared__ int wsum[32];
    int i0 = b * 4096 + t * 4;
    int v[4], s = 0;
#pragma unroll
    for (int j = 0; j < 4; j++) {
        v[j] = (i0 + j < Nn) ? g_deg_r[r * Nn + i0 + j] : 0;
        s += v[j];
    }
    int x = s;
#pragma unroll
    for (int o = 1; o < 32; o <<= 1) {
        int y = __shfl_up_sync(0xffffffffu, x, o);
        if (lane >= o) x += y;
    }
    if (lane == 31) wsum[w] = x;
    __syncthreads();
    if (w == 0) {
        int s2 = wsum[lane];
#pragma unroll
        for (int o = 1; o < 32; o <<= 1) {
            int y = __shfl_up_sync(0xffffffffu, s2, o);
            if (lane >= o) s2 += y;
        }
        wsum[lane] = s2;
    }
    __syncthreads();
    int woff = (w == 0) ? 0 : wsum[w - 1];
    int run = woff + x - s;
#pragma unroll
    for (int j = 0; j < 4; j++) {
        if (i0 + j < Nn) g_row_ptr[r * (Nn + 1) + i0 + j] = run;
        run += v[j];
    }
    if (t == 1023) g_blksum[r * NBLK + b] = woff + x;
}
__global__ void k_scan2() {
    int t = threadIdx.x, lane = t & 31, w = t >> 5;
    int v = (lane < NBLK) ? g_blksum[w * NBLK + lane] : 0;
    int x = v;
#pragma unroll
    for (int o = 1; o < 32; o <<= 1) {
        int y = __shfl_up_sync(0xffffffffu, x, o);
        if (lane >= o) x += y;
    }
    if (lane < NBLK) g_blksum[w * NBLK + lane] = x - v;
    if (lane == NBLK - 1) g_row_ptr[w * (Nn + 1) + Nn] = x;
}
__global__ __launch_bounds__(1024) void k_scan3() {
    int r = blockIdx.y, b = blockIdx.x;
    int off = g_blksum[r * NBLK + b];
    int i0 = b * 4096 + threadIdx.x * 4;
#pragma unroll
    for (int j = 0; j < 4; j++) {
        int i = i0 + j;
        if (i < Nn) {
            int p = g_row_ptr[r * (Nn + 1) + i] + off;
            g_row_ptr[r * (Nn + 1) + i] = p;
            g_cursor[r * Nn + i] = p;
        }
    }
}

// scatter with inline symmetric normalization (rsqrt of degrees)
__global__ void k_scatter(const int* __restrict__ ei) {
    int idx = blockIdx.x * blockDim.x + threadIdx.x;
    if (idx >= Rr * Ee) return;
    int r = idx / Ee, e = idx - r * Ee;
    const int* base = ei + (size_t)r * 2 * Ee;
    int row = base[e];
    int col = base[Ee + e];
    int pos = atomicAdd(&g_cursor[r * Nn + row], 1);
    float dr = rsqrtf(fmaxf((float)g_deg_r[r * Nn + row], 1.0f));
    float dc = rsqrtf(fmaxf((float)g_deg_c[r * Nn + col], 1.0f));
    g_edge[(size_t)r * Ee + pos] = make_int2(col, __float_as_int(dr * dc));
}

// ---------------- fp32 -> fp16 conversion ------------------------------------
__global__ void k_cvt(const float* __restrict__ x, __half* __restrict__ dst) {
    int idx = blockIdx.x * blockDim.x + threadIdx.x;
    const int total = Nn * Hh / 4;
    if (idx >= total) return;
    float4 v = ((const float4*)x)[idx];
    __half2 p0 = __floats2half2_rn(v.x, v.y);
    __half2 p1 = __floats2half2_rn(v.z, v.w);
    uint2 u;
    u.x = *(const uint32_t*)&p0;
    u.y = *(const uint32_t*)&p1;
    ((uint2*)dst)[idx] = u;
}

// ---------------- SpMM: warp per row, fp16 gather, 4-edge pipelined ---------
__device__ __forceinline__ void fma8(float* acc, float w, const uint4& v) {
    const __half2* h = (const __half2*)&v;
    float2 f;
    f = __half22float2(h[0]); acc[0] += w * f.x; acc[1] += w * f.y;
    f = __half22float2(h[1]); acc[2] += w * f.x; acc[3] += w * f.y;
    f = __half22float2(h[2]); acc[4] += w * f.x; acc[5] += w * f.y;
    f = __half22float2(h[3]); acc[6] += w * f.x; acc[7] += w * f.y;
}

__global__ __launch_bounds__(256) void k_spmm(int use_h1) {
    int r = blockIdx.y;
    int n = blockIdx.x * 8 + (threadIdx.x >> 5);
    if (n >= Nn) return;
    int lane = threadIdx.x & 31;
    const uint4* __restrict__ src = (const uint4*)(use_h1 ? g_h1h : g_Xh);
    int beg = g_row_ptr[r * (Nn + 1) + n];
    int end = g_row_ptr[r * (Nn + 1) + n + 1];
    const int2* __restrict__ edges = g_edge + (size_t)r * Ee;
    float acc[8];
#pragma unroll
    for (int j = 0; j < 8; j++) acc[j] = 0.f;

    int e = beg;
    for (; e + 4 <= end; e += 4) {
        int2 d0 = __ldg(edges + e);
        int2 d1 = __ldg(edges + e + 1);
        int2 d2 = __ldg(edges + e + 2);
        int2 d3 = __ldg(edges + e + 3);
        uint4 v0 = __ldg(src + ((size_t)d0.x << 5) + lane);
        uint4 v1 = __ldg(src + ((size_t)d1.x << 5) + lane);
        uint4 v2 = __ldg(src + ((size_t)d2.x << 5) + lane);
        uint4 v3 = __ldg(src + ((size_t)d3.x << 5) + lane);
        fma8(acc, __int_as_float(d0.y), v0);
        fma8(acc, __int_as_float(d1.y), v1);
        fma8(acc, __int_as_float(d2.y), v2);
        fma8(acc, __int_as_float(d3.y), v3);
    }
    for (; e < end; ++e) {
        int2 d = __ldg(edges + e);
        uint4 v = __ldg(src + ((size_t)d.x << 5) + lane);
        fma8(acc, __int_as_float(d.y), v);
    }

    __half2 p0 = __floats2half2_rn(acc[0], acc[1]);
    __half2 p1 = __floats2half2_rn(acc[2], acc[3]);
    __half2 p2 = __floats2half2_rn(acc[4], acc[5]);
    __half2 p3 = __floats2half2_rn(acc[6], acc[7]);
    uint4 o;
    o.x = *(const uint32_t*)&p0; o.y = *(const uint32_t*)&p1;
    o.z = *(const uint32_t*)&p2; o.w = *(const uint32_t*)&p3;
    g_S16[((size_t)r * Nn + n) * 32 + lane] = o;
}

// ---------------- W transpose to n-major fp16: B16[r][n][k] -----------------
__global__ void k_cvtW(const float* __restrict__ W) {
    int idx = blockIdx.x * blockDim.x + threadIdx.x;
    if (idx >= Rr * 256 * 256) return;
    int r = idx >> 16;
    int n = (idx >> 8) & 255;
    int k = idx & 255;
    float w = W[((size_t)r << 16) + ((size_t)k << 8) + n];
    size_t o = ((size_t)r << 16) + ((size_t)n << 8) + k;
    ((unsigned short*)g_B16)[o] = __half_as_ushort(__float2half_rn(w));
}

// ---------------- GEMM: Hh[r] = ReLU(S[r] @ W[r]), fp16 single --------------
// K-chunked (64) double-buffered A+B via cp.async; 72KB smem -> 3 CTA/SM.
// Epilogue: stage fp16 tile in smem, coalesced 16B stores to g_Hh.
#define CH_STRIDE 72                       // halfs per row (64 + 8 pad)
#define CHSZ (128 * CH_STRIDE * 2)         // 18432 B per chunk part
#define STG  (2 * CHSZ)                    // A + B per stage = 36864
#define SMEM_GEMM (2 * STG)                // 73728
#define EP_STRIDE 136                      // epilogue halfs per row (128 + 8 pad)

__global__ __launch_bounds__(256) void k_gemm() {
    extern __shared__ char smem[];
    uint32_t sb = smem_to_u32(smem);
    int tid = threadIdx.x, lane = tid & 31, wid = tid >> 5;
    int wm = wid >> 1, wn = wid & 1;
    int r = blockIdx.z, m0 = blockIdx.x * 128, n0 = blockIdx.y * 128;

    auto issue = [&](int kc) {
        uint32_t base = sb + (kc & 1) * STG;
        const uint4* bp = g_B16 + ((size_t)(r * 256 + n0)) * 32 + kc * 8;
#pragma unroll
        for (int j = 0; j < 4; j++) {
            int lin = tid + j * 256;
            int row = lin >> 3, ch = lin & 7;
            uint32_t so = row * (CH_STRIDE * 2) + ch * 16;
            int gm = m0 + row;
            int sz = (gm < Nn) ? 16 : 0;
            int gmc = (gm < Nn) ? gm : (Nn - 1);
            cp16(base + so, g_S16 + ((size_t)r * Nn + gmc) * 32 + kc * 8 + ch, sz);
            cp16(base + CHSZ + so, bp + row * 32 + ch, 16);
        }
    };

    issue(0);
    asm volatile("cp.async.commit_group;" ::: "memory");

    float acc[2][8][4];
#pragma unroll
    for (int a = 0; a < 2; a++)
#pragma unroll
        for (int b = 0; b < 8; b++)
#pragma unroll
            for (int c = 0; c < 4; c++) acc[a][b][c] = 0.f;

    int krow = lane & 15;
    int kof  = (lane >> 4) * 8;

    for (int kc = 0; kc < 4; kc++) {
        if (kc < 3) {
            issue(kc + 1);
            asm volatile("cp.async.commit_group;" ::: "memory");
            asm volatile("cp.async.wait_group 1;" ::: "memory");
        } else {
            asm volatile("cp.async.wait_group 0;" ::: "memory");
        }
        __syncthreads();

        uint32_t ab = sb + (kc & 1) * STG;
        uint32_t bb = ab + CHSZ;
#pragma unroll
        for (int kk = 0; kk < 4; kk++) {
            uint32_t afr[2][4], bfr[4][4];
            uint32_t a_off = (wm * 32 + krow) * (CH_STRIDE * 2) + (kk * 16 + kof) * 2;
            ldsm4(afr[0], ab + a_off);
            ldsm4(afr[1], ab + a_off + 16 * (CH_STRIDE * 2));
#pragma unroll
            for (int nq = 0; nq < 4; nq++) {
                uint32_t b_off = (wn * 64 + nq * 16 + krow) * (CH_STRIDE * 2) + (kk * 16 + kof) * 2;
                ldsm4(bfr[nq], bb + b_off);
            }
#pragma unroll
            for (int mt = 0; mt < 2; mt++) {
#pragma unroll
                for (int nq = 0; nq < 4; nq++) {
                    mma_f16(acc[mt][nq * 2],     afr[mt], bfr[nq][0], bfr[nq][2]);
                    mma_f16(acc[mt][nq * 2 + 1], afr[mt], bfr[nq][1], bfr[nq][3]);
                }
            }
        }
        __syncthreads();
    }

    // ---- epilogue: pack fp16 tile in smem, then coalesced stores ----------
    int rbase = wm * 32 + (lane >> 2);
    int cbase = wn * 64 + (lane & 3) * 2;
#pragma unroll
    for (int mt = 0; mt < 2; mt++) {
#pragma unroll
        for (int nn = 0; nn < 8; nn++) {
            float* c = acc[mt][nn];
            int row = rbase + mt * 16;
            int col = cbase + nn * 8;
            __half2 v01 = __floats2half2_rn(fmaxf(c[0], 0.f), fmaxf(c[1], 0.f));
            __half2 v23 = __floats2half2_rn(fmaxf(c[2], 0.f), fmaxf(c[3], 0.f));
            *(__half2*)(smem + (size_t)row * (EP_STRIDE * 2) + col * 2) = v01;
            *(__half2*)(smem + (size_t)(row + 8) * (EP_STRIDE * 2) + col * 2) = v23;
        }
    }
    __syncthreads();
#pragma unroll
    for (int j = 0; j < 8; j++) {
        int lin = tid + j * 256;
        int row = lin >> 4, ch = lin & 15;
        int gm = m0 + row;
        if (gm < Nn) {
            uint4 v = *(const uint4*)(smem + (size_t)row * (EP_STRIDE * 2) + ch * 16);
            *(uint4*)(g_Hh + ((size_t)r * Nn + gm) * Hh + n0 + ch * 8) = v;
        }
    }
}

// ---------------- layer-1 mean: h1 = 0.25 * sum_r Hh[r] (fp16 in/out) -------
__global__ void k_mean() {
    int idx = blockIdx.x * blockDim.x + threadIdx.x;
    const int total = Nn * Hh / 8;   // 8 halfs per uint4
    if (idx >= total) return;
    const uint4* h = (const uint4*)g_Hh;
    size_t off = (size_t)Nn * Hh / 8;
    uint4 a = h[idx], b = h[idx + off], c = h[idx + 2 * off], d = h[idx + 3 * off];
    const __half2* a2 = (const __half2*)&a;
    const __half2* b2 = (const __half2*)&b;
    const __half2* c2 = (const __half2*)&c;
    const __half2* d2 = (const __half2*)&d;
    uint4 o;
    __half2* o2 = (__half2*)&o;
#pragma unroll
    for (int j = 0; j < 4; j++) {
        float2 fa = __half22float2(a2[j]), fb = __half22float2(b2[j]);
        float2 fc = __half22float2(c2[j]), fd = __half22float2(d2[j]);
        o2[j] = __floats2half2_rn(0.25f * (fa.x + fb.x + fc.x + fd.x),
                                  0.25f * (fa.y + fb.y + fc.y + fd.y));
    }
    ((uint4*)g_h1h)[idx] = o;
}

// ---------------- attention + residual fusion + output GEMM -----------------
__global__ __launch_bounds__(256) void k_attn(const float* __restrict__ att_q,
                                              const float* __restrict__ tau_p,
                                              const float* __restrict__ W_out,
                                              const float* __restrict__ b_out,
                                              float* __restrict__ out) {
    int n = blockIdx.x * 8 + (threadIdx.x >> 5);
    if (n >= Nn) return;
    int lane = threadIdx.x & 31;

    float2 q2[4];
#pragma unroll
    for (int j = 0; j < 4; j++) {
        int c = 2 * lane + 64 * j;
        q2[j] = make_float2(att_q[c], att_q[c + 1]);
    }

    float v[4][8];
    float sc[4];
#pragma unroll
    for (int r = 0; r < 4; r++) {
        const __half2* h = (const __half2*)(g_Hh + ((size_t)r * Nn + n) * Hh);
        float s = 0.f;
#pragma unroll
        for (int j = 0; j < 4; j++) {
            float2 f = __half22float2(h[lane + 32 * j]);
            v[r][2 * j] = f.x; v[r][2 * j + 1] = f.y;
            s += f.x * q2[j].x + f.y * q2[j].y;
        }
#pragma unroll
        for (int o = 16; o; o >>= 1) s += __shfl_xor_sync(0xffffffffu, s, o);
        sc[r] = s;
    }
    float tc = fminf(fmaxf(tau_p[0], 0.5f), 5.0f);
    float inv = 1.0f / tc;
    float s0 = sc[0] * inv, s1 = sc[1] * inv, s2 = sc[2] * inv, s3 = sc[3] * inv;
    float m = fmaxf(fmaxf(s0, s1), fmaxf(s2, s3));
    float e0 = expf(s0 - m), e1 = expf(s1 - m), e2 = expf(s2 - m), e3 = expf(s3 - m);
    float se = e0 + e1 + e2 + e3;
    float al[4] = {e0 / se, e1 / se, e2 / se, e3 / se};

    float h2[8];
#pragma unroll
    for (int k = 0; k < 8; k++)
        h2[k] = (0.25f + al[0]) * v[0][k] + (0.25f + al[1]) * v[1][k] +
                (0.25f + al[2]) * v[2][k] + (0.25f + al[3]) * v[3][k];

    float acc[16];
#pragma unroll
    for (int c = 0; c < 16; c++) acc[c] = 0.f;
#pragma unroll
    for (int j = 0; j < 4; j++) {
#pragma unroll
        for (int t = 0; t < 2; t++) {
            int idx = 2 * lane + 64 * j + t;
            const float4* wr = (const float4*)(W_out + (size_t)idx * 16);
            float4 w0 = wr[0], w1 = wr[1], w2 = wr[2], w3 = wr[3];
            float hv = h2[2 * j + t];
            acc[0]  += hv * w0.x; acc[1]  += hv * w0.y; acc[2]  += hv * w0.z; acc[3]  += hv * w0.w;
            acc[4]  += hv * w1.x; acc[5]  += hv * w1.y; acc[6]  += hv * w1.z; acc[7]  += hv * w1.w;
            acc[8]  += hv * w2.x; acc[9]  += hv * w2.y; acc[10] += hv * w2.z; acc[11] += hv * w2.w;
            acc[12] += hv * w3.x; acc[13] += hv * w3.y; acc[14] += hv * w3.z; acc[15] += hv * w3.w;
        }
    }
#pragma unroll
    for (int c = 0; c < 16; c++)
#pragma unroll
        for (int o = 16; o; o >>= 1) acc[c] += __shfl_xor_sync(0xffffffffu, acc[c], o);

    if (lane < 16) {
        float lg = 0.f;
#pragma unroll
        for (int c = 0; c < 16; c++)
            if (lane == c) lg = acc[c];
        out[(size_t)n * Cc + lane] = lg + b_out[lane];
    }
    if (lane < 4) {
        float a = al[0];
        if (lane == 1) a = al[1];
        if (lane == 2) a = al[2];
        if (lane == 3) a = al[3];
        out[(size_t)Nn * Cc + (size_t)n * Rr + lane] = a;
    }
}

// ---------------- launch (serial) --------------------------------------------
extern "C" void kernel_launch(void* const* d_in, const int* in_sizes, int n_in,
                              void* d_out, int out_size) {
    const float* X     = (const float*)d_in[0];
    const int*   EI    = (const int*)d_in[1];
    const float* W1    = (const float*)d_in[2];
    const float* W2    = (const float*)d_in[3];
    const float* att_q = (const float*)d_in[4];
    const float* tau   = (const float*)d_in[5];
    const float* W_out = (const float*)d_in[6];
    const float* b_out = (const float*)d_in[7];
    float* out = (float*)d_out;
    (void)in_sizes; (void)n_in; (void)out_size;

    cudaFuncSetAttribute(k_gemm, cudaFuncAttributeMaxDynamicSharedMemorySize, SMEM_GEMM);

    // CSR build
    k_zero_deg<<<(Rr * Nn + 255) / 256, 256>>>();
    k_hist<<<(Rr * Ee + 255) / 256, 256>>>(EI);
    k_scan1<<<dim3(NBLK, Rr), 1024>>>();
    k_scan2<<<1, 128>>>();
    k_scan3<<<dim3(NBLK, Rr), 1024>>>();
    k_scatter<<<(Rr * Ee + 255) / 256, 256>>>(EI);

    // fp16 copy of X for gathers
    __half* xh;
    cudaGetSymbolAddress((void**)&xh, g_Xh);
    k_cvt<<<(Nn * Hh / 4 + 255) / 256, 256>>>(X, xh);

    dim3 spmm_grid((Nn + 7) / 8, Rr);
    dim3 gemm_grid((Nn + 127) / 128, Hh / 128, Rr);

    // Layer 1
    k_spmm<<<spmm_grid, 256>>>(0);
    k_cvtW<<<(Rr * 256 * 256 + 255) / 256, 256>>>(W1);
    k_gemm<<<gemm_grid, 256, SMEM_GEMM>>>();
    k_mean<<<(Nn * Hh / 8 + 255) / 256, 256>>>();

    // Layer 2
    k_spmm<<<spmm_grid, 256>>>(1);
    k_cvtW<<<(Rr * 256 * 256 + 255) / 256, 256>>>(W2);
    k_gemm<<<gemm_grid, 256, SMEM_GEMM>>>();

    // Attention + output head
    k_attn<<<(Nn + 7) / 8, 256>>>(att_q, tau, W_out, b_out, out);
}

// round 16
// speedup vs baseline: 1.4443x; 1.0303x over previous
#include <cuda_runtime.h>
#include <cuda_bf16.h>
#include <cuda_fp16.h>
#include <cstdint>
#include <math.h>

#define Nn 50000
#define Rr 4
#define Ee 1600000
#define Hh 256
#define Cc 16
#define NBLK 13   // ceil(50000 / 4096)

// ---------------- scratch (device globals; no runtime allocation) ----------
__device__ int   g_deg_r[Rr * Nn];
__device__ int   g_deg_c[Rr * Nn];
__device__ int   g_row_ptr[Rr * (Nn + 1)];
__device__ int   g_blksum[Rr * NBLK];
__device__ unsigned short g_rank[(size_t)Rr * Ee];  // edge rank within its row
__device__ int2  g_edge[(size_t)Rr * Ee];           // packed {col, wgt_bits}
// fp16 gather sources
__device__ __half g_Xh[(size_t)Nn * Hh];
__device__ __half g_h1h[(size_t)Nn * Hh];
// SpMM outputs packed fp16: [R][N][256] fp16 = 32 uint4 per row
__device__ uint4 g_S16[(size_t)Rr * Nn * 32];
// fp16 W transposed to n-major: [layer][R][n=256][k=256]
__device__ uint4 g_B16[2 * Rr * 256 * 32];
// per-relation hidden states, fp16 (coalesced-stored by GEMM epilogue)
__device__ __half g_Hh[(size_t)Rr * Nn * Hh];

// ---------------- low-level helpers (all base-arch PTX) ---------------------
__device__ __forceinline__ uint32_t smem_to_u32(const void* p) {
    uint32_t a;
    asm("{ .reg .u64 t; cvta.to.shared.u64 t, %1; cvt.u32.u64 %0, t; }" : "=r"(a) : "l"(p));
    return a;
}
__device__ __forceinline__ void cp16(uint32_t dst, const void* src, int sz) {
    asm volatile("cp.async.cg.shared.global [%0], [%1], 16, %2;"
                 :: "r"(dst), "l"(src), "r"(sz));
}
__device__ __forceinline__ void ldsm4(uint32_t* r, uint32_t addr) {
    asm volatile("ldmatrix.sync.aligned.m8n8.x4.shared.b16 {%0,%1,%2,%3}, [%4];"
                 : "=r"(r[0]), "=r"(r[1]), "=r"(r[2]), "=r"(r[3]) : "r"(addr));
}
__device__ __forceinline__ void mma_f16(float* c, const uint32_t* a, uint32_t b0, uint32_t b1) {
    asm volatile("mma.sync.aligned.m16n8k16.row.col.f32.f16.f16.f32 "
                 "{%0,%1,%2,%3}, {%4,%5,%6,%7}, {%8,%9}, {%0,%1,%2,%3};"
                 : "+f"(c[0]), "+f"(c[1]), "+f"(c[2]), "+f"(c[3])
                 : "r"(a[0]), "r"(a[1]), "r"(a[2]), "r"(a[3]), "r"(b0), "r"(b1));
}

// ---------------- CSR construction ------------------------------------------
__global__ void k_zero_deg() {
    int i = blockIdx.x * blockDim.x + threadIdx.x;
    if (i < Rr * Nn) { g_deg_r[i] = 0; g_deg_c[i] = 0; }
}
// hist also records each edge's rank within its row (atomic return value)
__global__ void k_hist(const int* __restrict__ ei) {
    int idx = blockIdx.x * blockDim.x + threadIdx.x;
    if (idx >= Rr * Ee) return;
    int r = idx / Ee, e = idx - r * Ee;
    const int* base = ei + (size_t)r * 2 * Ee;
    int rank = atomicAdd(&g_deg_r[r * Nn + base[e]], 1);
    g_rank[idx] = (unsigned short)rank;
    atomicAdd(&g_deg_c[r * Nn + base[Ee + e]], 1);
}

// ---- multi-block scan ---------------------------------------------------
__global__ __launch_bounds__(1024) void k_scan1() {
    int r = blockIdx.y, b = blockIdx.x;
    int t = threadIdx.x, lane = t & 31, w = t >> 5;
    __shared__ int wsum[32];
    int i0 = b * 4096 + t * 4;
    int v[4], s = 0;
#pragma unroll
    for (int j = 0; j < 4; j++) {
        v[j] = (i0 + j < Nn) ? g_deg_r[r * Nn + i0 + j] : 0;
        s += v[j];
    }
    int x = s;
#pragma unroll
    for (int o = 1; o < 32; o <<= 1) {
        int y = __shfl_up_sync(0xffffffffu, x, o);
        if (lane >= o) x += y;
    }
    if (lane == 31) wsum[w] = x;
    __syncthreads();
    if (w == 0) {
        int s2 = wsum[lane];
#pragma unroll
        for (int o = 1; o < 32; o <<= 1) {
            int y = __shfl_up_sync(0xffffffffu, s2, o);
            if (lane >= o) s2 += y;
        }
        wsum[lane] = s2;
    }
    __syncthreads();
    int woff = (w == 0) ? 0 : wsum[w - 1];
    int run = woff + x - s;
#pragma unroll
    for (int j = 0; j < 4; j++) {
        if (i0 + j < Nn) g_row_ptr[r * (Nn + 1) + i0 + j] = run;
        run += v[j];
    }
    if (t == 1023) g_blksum[r * NBLK + b] = woff + x;
}
__global__ void k_scan2() {
    int t = threadIdx.x, lane = t & 31, w = t >> 5;
    int v = (lane < NBLK) ? g_blksum[w * NBLK + lane] : 0;
    int x = v;
#pragma unroll
    for (int o = 1; o < 32; o <<= 1) {
        int y = __shfl_up_sync(0xffffffffu, x, o);
        if (lane >= o) x += y;
    }
    if (lane < NBLK) g_blksum[w * NBLK + lane] = x - v;
    if (lane == NBLK - 1) g_row_ptr[w * (Nn + 1) + Nn] = x;
}
__global__ __launch_bounds__(1024) void k_scan3() {
    int r = blockIdx.y, b = blockIdx.x;
    int off = g_blksum[r * NBLK + b];
    int i0 = b * 4096 + threadIdx.x * 4;
#pragma unroll
    for (int j = 0; j < 4; j++) {
        int i = i0 + j;
        if (i < Nn) g_row_ptr[r * (Nn + 1) + i] += off;
    }
}

// scatter with NO atomics: pos = row_ptr[row] + rank[e]
__global__ void k_scatter(const int* __restrict__ ei) {
    int idx = blockIdx.x * blockDim.x + threadIdx.x;
    if (idx >= Rr * Ee) return;
    int r = idx / Ee, e = idx - r * Ee;
    const int* base = ei + (size_t)r * 2 * Ee;
    int row = base[e];
    int col = base[Ee + e];
    int pos = g_row_ptr[r * (Nn + 1) + row] + (int)g_rank[idx];
    float dr = rsqrtf(fmaxf((float)g_deg_r[r * Nn + row], 1.0f));
    float dc = rsqrtf(fmaxf((float)g_deg_c[r * Nn + col], 1.0f));
    g_edge[(size_t)r * Ee + pos] = make_int2(col, __float_as_int(dr * dc));
}

// ---------------- merged prep: X->fp16 + both W transposes ------------------
#define XCVT (Nn * Hh / 4)                 // 3,200,000 float4 groups
#define WCVT (Rr * 256 * 256)              // 262,144 per layer
__global__ void k_prep(const float* __restrict__ X,
                       const float* __restrict__ W1,
                       const float* __restrict__ W2) {
    int idx = blockIdx.x * blockDim.x + threadIdx.x;
    if (idx < XCVT) {
        float4 v = ((const float4*)X)[idx];
        __half2 p0 = __floats2half2_rn(v.x, v.y);
        __half2 p1 = __floats2half2_rn(v.z, v.w);
        uint2 u;
        u.x = *(const uint32_t*)&p0;
        u.y = *(const uint32_t*)&p1;
        ((uint2*)g_Xh)[idx] = u;
        return;
    }
    int wi = idx - XCVT;
    if (wi >= 2 * WCVT) return;
    int layer = wi >= WCVT;
    int li = wi - layer * WCVT;
    int r = li >> 16;
    int n = (li >> 8) & 255;
    int k = li & 255;
    const float* W = layer ? W2 : W1;
    float w = W[((size_t)r << 16) + ((size_t)k << 8) + n];
    size_t o = ((size_t)(layer * Rr + r) << 16) + ((size_t)n << 8) + k;
    ((unsigned short*)g_B16)[o] = __half_as_ushort(__float2half_rn(w));
}

// ---------------- SpMM: warp per row, fp16 gather, 4-edge pipelined ---------
__device__ __forceinline__ void fma8(float* acc, float w, const uint4& v) {
    const __half2* h = (const __half2*)&v;
    float2 f;
    f = __half22float2(h[0]); acc[0] += w * f.x; acc[1] += w * f.y;
    f = __half22float2(h[1]); acc[2] += w * f.x; acc[3] += w * f.y;
    f = __half22float2(h[2]); acc[4] += w * f.x; acc[5] += w * f.y;
    f = __half22float2(h[3]); acc[6] += w * f.x; acc[7] += w * f.y;
}

__global__ __launch_bounds__(256) void k_spmm(int use_h1) {
    int r = blockIdx.y;
    int n = blockIdx.x * 8 + (threadIdx.x >> 5);
    if (n >= Nn) return;
    int lane = threadIdx.x & 31;
    const uint4* __restrict__ src = (const uint4*)(use_h1 ? g_h1h : g_Xh);
    int beg = g_row_ptr[r * (Nn + 1) + n];
    int end = g_row_ptr[r * (Nn + 1) + n + 1];
    const int2* __restrict__ edges = g_edge + (size_t)r * Ee;
    float acc[8];
#pragma unroll
    for (int j = 0; j < 8; j++) acc[j] = 0.f;

    int e = beg;
    for (; e + 4 <= end; e += 4) {
        int2 d0 = __ldg(edges + e);
        int2 d1 = __ldg(edges + e + 1);
        int2 d2 = __ldg(edges + e + 2);
        int2 d3 = __ldg(edges + e + 3);
        uint4 v0 = __ldg(src + ((size_t)d0.x << 5) + lane);
        uint4 v1 = __ldg(src + ((size_t)d1.x << 5) + lane);
        uint4 v2 = __ldg(src + ((size_t)d2.x << 5) + lane);
        uint4 v3 = __ldg(src + ((size_t)d3.x << 5) + lane);
        fma8(acc, __int_as_float(d0.y), v0);
        fma8(acc, __int_as_float(d1.y), v1);
        fma8(acc, __int_as_float(d2.y), v2);
        fma8(acc, __int_as_float(d3.y), v3);
    }
    for (; e < end; ++e) {
        int2 d = __ldg(edges + e);
        uint4 v = __ldg(src + ((size_t)d.x << 5) + lane);
        fma8(acc, __int_as_float(d.y), v);
    }

    __half2 p0 = __floats2half2_rn(acc[0], acc[1]);
    __half2 p1 = __floats2half2_rn(acc[2], acc[3]);
    __half2 p2 = __floats2half2_rn(acc[4], acc[5]);
    __half2 p3 = __floats2half2_rn(acc[6], acc[7]);
    uint4 o;
    o.x = *(const uint32_t*)&p0; o.y = *(const uint32_t*)&p1;
    o.z = *(const uint32_t*)&p2; o.w = *(const uint32_t*)&p3;
    g_S16[((size_t)r * Nn + n) * 32 + lane] = o;
}

// ---------------- GEMM: Hh[r] = ReLU(S[r] @ W[layer][r]), fp16 single -------
// K-chunked (64) double-buffered A+B via cp.async; 72KB smem.
// Epilogue: stage fp16 tile in smem, coalesced 16B stores to g_Hh.
#define CH_STRIDE 72                       // halfs per row (64 + 8 pad)
#define CHSZ (128 * CH_STRIDE * 2)         // 18432 B per chunk part
#define STG  (2 * CHSZ)                    // A + B per stage = 36864
#define SMEM_GEMM (2 * STG)                // 73728
#define EP_STRIDE 136                      // epilogue halfs per row (128 + 8 pad)

__global__ __launch_bounds__(256) void k_gemm(int layer) {
    extern __shared__ char smem[];
    uint32_t sb = smem_to_u32(smem);
    int tid = threadIdx.x, lane = tid & 31, wid = tid >> 5;
    int wm = wid >> 1, wn = wid & 1;
    int r = blockIdx.z, m0 = blockIdx.x * 128, n0 = blockIdx.y * 128;

    auto issue = [&](int kc) {
        uint32_t base = sb + (kc & 1) * STG;
        const uint4* bp = g_B16 + ((size_t)((layer * Rr + r) * 256 + n0)) * 32 + kc * 8;
#pragma unroll
        for (int j = 0; j < 4; j++) {
            int lin = tid + j * 256;
            int row = lin >> 3, ch = lin & 7;
            uint32_t so = row * (CH_STRIDE * 2) + ch * 16;
            int gm = m0 + row;
            int sz = (gm < Nn) ? 16 : 0;
            int gmc = (gm < Nn) ? gm : (Nn - 1);
            cp16(base + so, g_S16 + ((size_t)r * Nn + gmc) * 32 + kc * 8 + ch, sz);
            cp16(base + CHSZ + so, bp + row * 32 + ch, 16);
        }
    };

    issue(0);
    asm volatile("cp.async.commit_group;" ::: "memory");

    float acc[2][8][4];
#pragma unroll
    for (int a = 0; a < 2; a++)
#pragma unroll
        for (int b = 0; b < 8; b++)
#pragma unroll
            for (int c = 0; c < 4; c++) acc[a][b][c] = 0.f;

    int krow = lane & 15;
    int kof  = (lane >> 4) * 8;

    for (int kc = 0; kc < 4; kc++) {
        if (kc < 3) {
            issue(kc + 1);
            asm volatile("cp.async.commit_group;" ::: "memory");
            asm volatile("cp.async.wait_group 1;" ::: "memory");
        } else {
            asm volatile("cp.async.wait_group 0;" ::: "memory");
        }
        __syncthreads();

        uint32_t ab = sb + (kc & 1) * STG;
        uint32_t bb = ab + CHSZ;
#pragma unroll
        for (int kk = 0; kk < 4; kk++) {
            uint32_t afr[2][4], bfr[4][4];
            uint32_t a_off = (wm * 32 + krow) * (CH_STRIDE * 2) + (kk * 16 + kof) * 2;
            ldsm4(afr[0], ab + a_off);
            ldsm4(afr[1], ab + a_off + 16 * (CH_STRIDE * 2));
#pragma unroll
            for (int nq = 0; nq < 4; nq++) {
                uint32_t b_off = (wn * 64 + nq * 16 + krow) * (CH_STRIDE * 2) + (kk * 16 + kof) * 2;
                ldsm4(bfr[nq], bb + b_off);
            }
#pragma unroll
            for (int mt = 0; mt < 2; mt++) {
#pragma unroll
                for (int nq = 0; nq < 4; nq++) {
                    mma_f16(acc[mt][nq * 2],     afr[mt], bfr[nq][0], bfr[nq][2]);
                    mma_f16(acc[mt][nq * 2 + 1], afr[mt], bfr[nq][1], bfr[nq][3]);
                }
            }
        }
        __syncthreads();
    }

    // ---- epilogue: pack fp16 tile in smem, then coalesced stores ----------
    int rbase = wm * 32 + (lane >> 2);
    int cbase = wn * 64 + (lane & 3) * 2;
#pragma unroll
    for (int mt = 0; mt < 2; mt++) {
#pragma unroll
        for (int nn = 0; nn < 8; nn++) {
            float* c = acc[mt][nn];
            int row = rbase + mt * 16;
            int col = cbase + nn * 8;
            __half2 v01 = __floats2half2_rn(fmaxf(c[0], 0.f), fmaxf(c[1], 0.f));
            __half2 v23 = __floats2half2_rn(fmaxf(c[2], 0.f), fmaxf(c[3], 0.f));
            *(__half2*)(smem + (size_t)row * (EP_STRIDE * 2) + col * 2) = v01;
            *(__half2*)(smem + (size_t)(row + 8) * (EP_STRIDE * 2) + col * 2) = v23;
        }
    }
    __syncthreads();
#pragma unroll
    for (int j = 0; j < 8; j++) {
        int lin = tid + j * 256;
        int row = lin >> 4, ch = lin & 15;
        int gm = m0 + row;
        if (gm < Nn) {
            uint4 v = *(const uint4*)(smem + (size_t)row * (EP_STRIDE * 2) + ch * 16);
            *(uint4*)(g_Hh + ((size_t)r * Nn + gm) * Hh + n0 + ch * 8) = v;
        }
    }
}

// ---------------- layer-1 mean: h1 = 0.25 * sum_r Hh[r] (fp16 in/out) -------
__global__ void k_mean() {
    int idx = blockIdx.x * blockDim.x + threadIdx.x;
    const int total = Nn * Hh / 8;   // 8 halfs per uint4
    if (idx >= total) return;
    const uint4* h = (const uint4*)g_Hh;
    size_t off = (size_t)Nn * Hh / 8;
    uint4 a = h[idx], b = h[idx + off], c = h[idx + 2 * off], d = h[idx + 3 * off];
    const __half2* a2 = (const __half2*)&a;
    const __half2* b2 = (const __half2*)&b;
    const __half2* c2 = (const __half2*)&c;
    const __half2* d2 = (const __half2*)&d;
    uint4 o;
    __half2* o2 = (__half2*)&o;
#pragma unroll
    for (int j = 0; j < 4; j++) {
        float2 fa = __half22float2(a2[j]), fb = __half22float2(b2[j]);
        float2 fc = __half22float2(c2[j]), fd = __half22float2(d2[j]);
        o2[j] = __floats2half2_rn(0.25f * (fa.x + fb.x + fc.x + fd.x),
                                  0.25f * (fa.y + fb.y + fc.y + fd.y));
    }
    ((uint4*)g_h1h)[idx] = o;
}

// ---------------- attention + residual fusion + output GEMM -----------------
__global__ __launch_bounds__(256) void k_attn(const float* __restrict__ att_q,
                                              const float* __restrict__ tau_p,
                                              const float* __restrict__ W_out,
                                              const float* __restrict__ b_out,
                                              float* __restrict__ out) {
    int n = blockIdx.x * 8 + (threadIdx.x >> 5);
    if (n >= Nn) return;
    int lane = threadIdx.x & 31;

    float2 q2[4];
#pragma unroll
    for (int j = 0; j < 4; j++) {
        int c = 2 * lane + 64 * j;
        q2[j] = make_float2(att_q[c], att_q[c + 1]);
    }

    float v[4][8];
    float sc[4];
#pragma unroll
    for (int r = 0; r < 4; r++) {
        const __half2* h = (const __half2*)(g_Hh + ((size_t)r * Nn + n) * Hh);
        float s = 0.f;
#pragma unroll
        for (int j = 0; j < 4; j++) {
            float2 f = __half22float2(h[lane + 32 * j]);
            v[r][2 * j] = f.x; v[r][2 * j + 1] = f.y;
            s += f.x * q2[j].x + f.y * q2[j].y;
        }
#pragma unroll
        for (int o = 16; o; o >>= 1) s += __shfl_xor_sync(0xffffffffu, s, o);
        sc[r] = s;
    }
    float tc = fminf(fmaxf(tau_p[0], 0.5f), 5.0f);
    float inv = 1.0f / tc;
    float s0 = sc[0] * inv, s1 = sc[1] * inv, s2 = sc[2] * inv, s3 = sc[3] * inv;
    float m = fmaxf(fmaxf(s0, s1), fmaxf(s2, s3));
    float e0 = expf(s0 - m), e1 = expf(s1 - m), e2 = expf(s2 - m), e3 = expf(s3 - m);
    float se = e0 + e1 + e2 + e3;
    float al[4] = {e0 / se, e1 / se, e2 / se, e3 / se};

    float h2[8];
#pragma unroll
    for (int k = 0; k < 8; k++)
        h2[k] = (0.25f + al[0]) * v[0][k] + (0.25f + al[1]) * v[1][k] +
                (0.25f + al[2]) * v[2][k] + (0.25f + al[3]) * v[3][k];

    float acc[16];
#pragma unroll
    for (int c = 0; c < 16; c++) acc[c] = 0.f;
#pragma unroll
    for (int j = 0; j < 4; j++) {
#pragma unroll
        for (int t = 0; t < 2; t++) {
            int idx = 2 * lane + 64 * j + t;
            const float4* wr = (const float4*)(W_out + (size_t)idx * 16);
            float4 w0 = wr[0], w1 = wr[1], w2 = wr[2], w3 = wr[3];
            float hv = h2[2 * j + t];
            acc[0]  += hv * w0.x; acc[1]  += hv * w0.y; acc[2]  += hv * w0.z; acc[3]  += hv * w0.w;
            acc[4]  += hv * w1.x; acc[5]  += hv * w1.y; acc[6]  += hv * w1.z; acc[7]  += hv * w1.w;
            acc[8]  += hv * w2.x; acc[9]  += hv * w2.y; acc[10] += hv * w2.z; acc[11] += hv * w2.w;
            acc[12] += hv * w3.x; acc[13] += hv * w3.y; acc[14] += hv * w3.z; acc[15] += hv * w3.w;
        }
    }
#pragma unroll
    for (int c = 0; c < 16; c++)
#pragma unroll
        for (int o = 16; o; o >>= 1) acc[c] += __shfl_xor_sync(0xffffffffu, acc[c], o);

    if (lane < 16) {
        float lg = 0.f;
#pragma unroll
        for (int c = 0; c < 16; c++)
            if (lane == c) lg = acc[c];
        out[(size_t)n * Cc + lane] = lg + b_out[lane];
    }
    if (lane < 4) {
        float a = al[0];
        if (lane == 1) a = al[1];
        if (lane == 2) a = al[2];
        if (lane == 3) a = al[3];
        out[(size_t)Nn * Cc + (size_t)n * Rr + lane] = a;
    }
}

// ---------------- launch (serial) --------------------------------------------
extern "C" void kernel_launch(void* const* d_in, const int* in_sizes, int n_in,
                              void* d_out, int out_size) {
    const float* X     = (const float*)d_in[0];
    const int*   EI    = (const int*)d_in[1];
    const float* W1    = (const float*)d_in[2];
    const float* W2    = (const float*)d_in[3];
    const float* att_q = (const float*)d_in[4];
    const float* tau   = (const float*)d_in[5];
    const float* W_out = (const float*)d_in[6];
    const float* b_out = (const float*)d_in[7];
    float* out = (float*)d_out;
    (void)in_sizes; (void)n_in; (void)out_size;

    cudaFuncSetAttribute(k_gemm, cudaFuncAttributeMaxDynamicSharedMemorySize, SMEM_GEMM);

    // CSR build (rank recorded in hist; scatter is atomic-free)
    k_zero_deg<<<(Rr * Nn + 255) / 256, 256>>>();
    k_hist<<<(Rr * Ee + 255) / 256, 256>>>(EI);
    k_scan1<<<dim3(NBLK, Rr), 1024>>>();
    k_scan2<<<1, 128>>>();
    k_scan3<<<dim3(NBLK, Rr), 1024>>>();
    k_scatter<<<(Rr * Ee + 255) / 256, 256>>>(EI);

    // merged prep: X->fp16 + both W transposes
    k_prep<<<(XCVT + 2 * WCVT + 255) / 256, 256>>>(X, W1, W2);

    dim3 spmm_grid((Nn + 7) / 8, Rr);
    dim3 gemm_grid((Nn + 127) / 128, Hh / 128, Rr);

    // Layer 1
    k_spmm<<<spmm_grid, 256>>>(0);
    k_gemm<<<gemm_grid, 256, SMEM_GEMM>>>(0);
    k_mean<<<(Nn * Hh / 8 + 255) / 256, 256>>>();

    // Layer 2
    k_spmm<<<spmm_grid, 256>>>(1);
    k_gemm<<<gemm_grid, 256, SMEM_GEMM>>>(1);

    // Attention + output head
    k_attn<<<(Nn + 7) / 8, 256>>>(att_q, tau, W_out, b_out, out);
}

// round 17
// speedup vs baseline: 1.4509x; 1.0046x over previous
#include <cuda_runtime.h>
#include <cuda_bf16.h>
#include <cuda_fp16.h>
#include <cstdint>
#include <math.h>

#define Nn 50000
#define Rr 4
#define Ee 1600000
#define Hh 256
#define Cc 16
#define NBLK 13   // ceil(50000 / 4096)

// ---------------- scratch (device globals; no runtime allocation) ----------
__device__ int   g_deg_r[Rr * Nn];
__device__ int   g_deg_c[Rr * Nn];
__device__ int   g_row_ptr[Rr * (Nn + 1)];
__device__ int   g_blksum[Rr * NBLK];
__device__ unsigned short g_rank[(size_t)Rr * Ee];  // edge rank within its row
__device__ int2  g_edge[(size_t)Rr * Ee];           // packed {col, wgt_bits}
// fp16 gather sources
__device__ __half g_Xh[(size_t)Nn * Hh];
__device__ __half g_h1h[(size_t)Nn * Hh];
// SpMM outputs packed fp16: [R][N][256] fp16 = 32 uint4 per row
__device__ uint4 g_S16[(size_t)Rr * Nn * 32];
// fp16 W transposed to n-major: [layer][R][n=256][k=256]
__device__ uint4 g_B16[2 * Rr * 256 * 32];
// per-relation hidden states, fp16 (coalesced-stored by GEMM epilogue)
__device__ __half g_Hh[(size_t)Rr * Nn * Hh];

// ---------------- low-level helpers (all base-arch PTX) ---------------------
__device__ __forceinline__ uint32_t smem_to_u32(const void* p) {
    uint32_t a;
    asm("{ .reg .u64 t; cvta.to.shared.u64 t, %1; cvt.u32.u64 %0, t; }" : "=r"(a) : "l"(p));
    return a;
}
__device__ __forceinline__ void cp16(uint32_t dst, const void* src, int sz) {
    asm volatile("cp.async.cg.shared.global [%0], [%1], 16, %2;"
                 :: "r"(dst), "l"(src), "r"(sz));
}
__device__ __forceinline__ void ldsm4(uint32_t* r, uint32_t addr) {
    asm volatile("ldmatrix.sync.aligned.m8n8.x4.shared.b16 {%0,%1,%2,%3}, [%4];"
                 : "=r"(r[0]), "=r"(r[1]), "=r"(r[2]), "=r"(r[3]) : "r"(addr));
}
__device__ __forceinline__ void mma_f16(float* c, const uint32_t* a, uint32_t b0, uint32_t b1) {
    asm volatile("mma.sync.aligned.m16n8k16.row.col.f32.f16.f16.f32 "
                 "{%0,%1,%2,%3}, {%4,%5,%6,%7}, {%8,%9}, {%0,%1,%2,%3};"
                 : "+f"(c[0]), "+f"(c[1]), "+f"(c[2]), "+f"(c[3])
                 : "r"(a[0]), "r"(a[1]), "r"(a[2]), "r"(a[3]), "r"(b0), "r"(b1));
}

// ---------------- CSR construction ------------------------------------------
__global__ void k_zero_deg() {
    int i = blockIdx.x * blockDim.x + threadIdx.x;
    if (i < Rr * Nn) { g_deg_r[i] = 0; g_deg_c[i] = 0; }
}
// hist also records each edge's rank within its row (atomic return value)
__global__ void k_hist(const int* __restrict__ ei) {
    int idx = blockIdx.x * blockDim.x + threadIdx.x;
    if (idx >= Rr * Ee) return;
    int r = idx / Ee, e = idx - r * Ee;
    const int* base = ei + (size_t)r * 2 * Ee;
    int rank = atomicAdd(&g_deg_r[r * Nn + base[e]], 1);
    g_rank[idx] = (unsigned short)rank;
    atomicAdd(&g_deg_c[r * Nn + base[Ee + e]], 1);
}

// ---- multi-block scan ---------------------------------------------------
__global__ __launch_bounds__(1024) void k_scan1() {
    int r = blockIdx.y, b = blockIdx.x;
    int t = threadIdx.x, lane = t & 31, w = t >> 5;
    __shared__ int wsum[32];
    int i0 = b * 4096 + t * 4;
    int v[4], s = 0;
#pragma unroll
    for (int j = 0; j < 4; j++) {
        v[j] = (i0 + j < Nn) ? g_deg_r[r * Nn + i0 + j] : 0;
        s += v[j];
    }
    int x = s;
#pragma unroll
    for (int o = 1; o < 32; o <<= 1) {
        int y = __shfl_up_sync(0xffffffffu, x, o);
        if (lane >= o) x += y;
    }
    if (lane == 31) wsum[w] = x;
    __syncthreads();
    if (w == 0) {
        int s2 = wsum[lane];
#pragma unroll
        for (int o = 1; o < 32; o <<= 1) {
            int y = __shfl_up_sync(0xffffffffu, s2, o);
            if (lane >= o) s2 += y;
        }
        wsum[lane] = s2;
    }
    __syncthreads();
    int woff = (w == 0) ? 0 : wsum[w - 1];
    int run = woff + x - s;
#pragma unroll
    for (int j = 0; j < 4; j++) {
        if (i0 + j < Nn) g_row_ptr[r * (Nn + 1) + i0 + j] = run;
        run += v[j];
    }
    if (t == 1023) g_blksum[r * NBLK + b] = woff + x;
}
__global__ void k_scan2() {
    int t = threadIdx.x, lane = t & 31, w = t >> 5;
    int v = (lane < NBLK) ? g_blksum[w * NBLK + lane] : 0;
    int x = v;
#pragma unroll
    for (int o = 1; o < 32; o <<= 1) {
        int y = __shfl_up_sync(0xffffffffu, x, o);
        if (lane >= o) x += y;
    }
    if (lane < NBLK) g_blksum[w * NBLK + lane] = x - v;
    if (lane == NBLK - 1) g_row_ptr[w * (Nn + 1) + Nn] = x;
}
__global__ __launch_bounds__(1024) void k_scan3() {
    int r = blockIdx.y, b = blockIdx.x;
    int off = g_blksum[r * NBLK + b];
    int i0 = b * 4096 + threadIdx.x * 4;
#pragma unroll
    for (int j = 0; j < 4; j++) {
        int i = i0 + j;
        if (i < Nn) g_row_ptr[r * (Nn + 1) + i] += off;
    }
}

// scatter with NO atomics: pos = row_ptr[row] + rank[e]
__global__ void k_scatter(const int* __restrict__ ei) {
    int idx = blockIdx.x * blockDim.x + threadIdx.x;
    if (idx >= Rr * Ee) return;
    int r = idx / Ee, e = idx - r * Ee;
    const int* base = ei + (size_t)r * 2 * Ee;
    int row = base[e];
    int col = base[Ee + e];
    int pos = g_row_ptr[r * (Nn + 1) + row] + (int)g_rank[idx];
    float dr = rsqrtf(fmaxf((float)g_deg_r[r * Nn + row], 1.0f));
    float dc = rsqrtf(fmaxf((float)g_deg_c[r * Nn + col], 1.0f));
    g_edge[(size_t)r * Ee + pos] = make_int2(col, __float_as_int(dr * dc));
}

// ---------------- merged prep: X->fp16 + both W transposes ------------------
#define XCVT (Nn * Hh / 4)                 // 3,200,000 float4 groups
#define WCVT (Rr * 256 * 256)              // 262,144 per layer
__global__ void k_prep(const float* __restrict__ X,
                       const float* __restrict__ W1,
                       const float* __restrict__ W2) {
    int idx = blockIdx.x * blockDim.x + threadIdx.x;
    if (idx < XCVT) {
        float4 v = ((const float4*)X)[idx];
        __half2 p0 = __floats2half2_rn(v.x, v.y);
        __half2 p1 = __floats2half2_rn(v.z, v.w);
        uint2 u;
        u.x = *(const uint32_t*)&p0;
        u.y = *(const uint32_t*)&p1;
        ((uint2*)g_Xh)[idx] = u;
        return;
    }
    int wi = idx - XCVT;
    if (wi >= 2 * WCVT) return;
    int layer = wi >= WCVT;
    int li = wi - layer * WCVT;
    int r = li >> 16;
    int n = (li >> 8) & 255;
    int k = li & 255;
    const float* W = layer ? W2 : W1;
    float w = W[((size_t)r << 16) + ((size_t)k << 8) + n];
    size_t o = ((size_t)(layer * Rr + r) << 16) + ((size_t)n << 8) + k;
    ((unsigned short*)g_B16)[o] = __half_as_ushort(__float2half_rn(w));
}

// ---------------- SpMM: warp per row, fp16 gather, 4-edge pipelined ---------
__device__ __forceinline__ void fma8(float* acc, float w, const uint4& v) {
    const __half2* h = (const __half2*)&v;
    float2 f;
    f = __half22float2(h[0]); acc[0] += w * f.x; acc[1] += w * f.y;
    f = __half22float2(h[1]); acc[2] += w * f.x; acc[3] += w * f.y;
    f = __half22float2(h[2]); acc[4] += w * f.x; acc[5] += w * f.y;
    f = __half22float2(h[3]); acc[6] += w * f.x; acc[7] += w * f.y;
}

__global__ __launch_bounds__(256) void k_spmm(int use_h1) {
    int r = blockIdx.y;
    int n = blockIdx.x * 8 + (threadIdx.x >> 5);
    if (n >= Nn) return;
    int lane = threadIdx.x & 31;
    const uint4* __restrict__ src = (const uint4*)(use_h1 ? g_h1h : g_Xh);
    int beg = g_row_ptr[r * (Nn + 1) + n];
    int end = g_row_ptr[r * (Nn + 1) + n + 1];
    const int2* __restrict__ edges = g_edge + (size_t)r * Ee;
    float acc[8];
#pragma unroll
    for (int j = 0; j < 8; j++) acc[j] = 0.f;

    int e = beg;
    for (; e + 4 <= end; e += 4) {
        int2 d0 = __ldg(edges + e);
        int2 d1 = __ldg(edges + e + 1);
        int2 d2 = __ldg(edges + e + 2);
        int2 d3 = __ldg(edges + e + 3);
        uint4 v0 = __ldg(src + ((size_t)d0.x << 5) + lane);
        uint4 v1 = __ldg(src + ((size_t)d1.x << 5) + lane);
        uint4 v2 = __ldg(src + ((size_t)d2.x << 5) + lane);
        uint4 v3 = __ldg(src + ((size_t)d3.x << 5) + lane);
        fma8(acc, __int_as_float(d0.y), v0);
        fma8(acc, __int_as_float(d1.y), v1);
        fma8(acc, __int_as_float(d2.y), v2);
        fma8(acc, __int_as_float(d3.y), v3);
    }
    for (; e < end; ++e) {
        int2 d = __ldg(edges + e);
        uint4 v = __ldg(src + ((size_t)d.x << 5) + lane);
        fma8(acc, __int_as_float(d.y), v);
    }

    __half2 p0 = __floats2half2_rn(acc[0], acc[1]);
    __half2 p1 = __floats2half2_rn(acc[2], acc[3]);
    __half2 p2 = __floats2half2_rn(acc[4], acc[5]);
    __half2 p3 = __floats2half2_rn(acc[6], acc[7]);
    uint4 o;
    o.x = *(const uint32_t*)&p0; o.y = *(const uint32_t*)&p1;
    o.z = *(const uint32_t*)&p2; o.w = *(const uint32_t*)&p3;
    g_S16[((size_t)r * Nn + n) * 32 + lane] = o;
}

// ---------------- GEMM: Hh[r] = ReLU(S[r] @ W[layer][r]), fp16 single -------
#define CH_STRIDE 72                       // halfs per row (64 + 8 pad)
#define CHSZ (128 * CH_STRIDE * 2)         // 18432 B per chunk part
#define STG  (2 * CHSZ)                    // A + B per stage = 36864
#define SMEM_GEMM (2 * STG)                // 73728
#define EP_STRIDE 136                      // epilogue halfs per row (128 + 8 pad)

__global__ __launch_bounds__(256) void k_gemm(int layer) {
    extern __shared__ char smem[];
    uint32_t sb = smem_to_u32(smem);
    int tid = threadIdx.x, lane = tid & 31, wid = tid >> 5;
    int wm = wid >> 1, wn = wid & 1;
    int r = blockIdx.z, m0 = blockIdx.x * 128, n0 = blockIdx.y * 128;

    auto issue = [&](int kc) {
        uint32_t base = sb + (kc & 1) * STG;
        const uint4* bp = g_B16 + ((size_t)((layer * Rr + r) * 256 + n0)) * 32 + kc * 8;
#pragma unroll
        for (int j = 0; j < 4; j++) {
            int lin = tid + j * 256;
            int row = lin >> 3, ch = lin & 7;
            uint32_t so = row * (CH_STRIDE * 2) + ch * 16;
            int gm = m0 + row;
            int sz = (gm < Nn) ? 16 : 0;
            int gmc = (gm < Nn) ? gm : (Nn - 1);
            cp16(base + so, g_S16 + ((size_t)r * Nn + gmc) * 32 + kc * 8 + ch, sz);
            cp16(base + CHSZ + so, bp + row * 32 + ch, 16);
        }
    };

    issue(0);
    asm volatile("cp.async.commit_group;" ::: "memory");

    float acc[2][8][4];
#pragma unroll
    for (int a = 0; a < 2; a++)
#pragma unroll
        for (int b = 0; b < 8; b++)
#pragma unroll
            for (int c = 0; c < 4; c++) acc[a][b][c] = 0.f;

    int krow = lane & 15;
    int kof  = (lane >> 4) * 8;

    for (int kc = 0; kc < 4; kc++) {
        if (kc < 3) {
            issue(kc + 1);
            asm volatile("cp.async.commit_group;" ::: "memory");
            asm volatile("cp.async.wait_group 1;" ::: "memory");
        } else {
            asm volatile("cp.async.wait_group 0;" ::: "memory");
        }
        __syncthreads();

        uint32_t ab = sb + (kc & 1) * STG;
        uint32_t bb = ab + CHSZ;
#pragma unroll
        for (int kk = 0; kk < 4; kk++) {
            uint32_t afr[2][4], bfr[4][4];
            uint32_t a_off = (wm * 32 + krow) * (CH_STRIDE * 2) + (kk * 16 + kof) * 2;
            ldsm4(afr[0], ab + a_off);
            ldsm4(afr[1], ab + a_off + 16 * (CH_STRIDE * 2));
#pragma unroll
            for (int nq = 0; nq < 4; nq++) {
                uint32_t b_off = (wn * 64 + nq * 16 + krow) * (CH_STRIDE * 2) + (kk * 16 + kof) * 2;
                ldsm4(bfr[nq], bb + b_off);
            }
#pragma unroll
            for (int mt = 0; mt < 2; mt++) {
#pragma unroll
                for (int nq = 0; nq < 4; nq++) {
                    mma_f16(acc[mt][nq * 2],     afr[mt], bfr[nq][0], bfr[nq][2]);
                    mma_f16(acc[mt][nq * 2 + 1], afr[mt], bfr[nq][1], bfr[nq][3]);
                }
            }
        }
        __syncthreads();
    }

    // ---- epilogue: pack fp16 tile in smem, then coalesced stores ----------
    int rbase = wm * 32 + (lane >> 2);
    int cbase = wn * 64 + (lane & 3) * 2;
#pragma unroll
    for (int mt = 0; mt < 2; mt++) {
#pragma unroll
        for (int nn = 0; nn < 8; nn++) {
            float* c = acc[mt][nn];
            int row = rbase + mt * 16;
            int col = cbase + nn * 8;
            __half2 v01 = __floats2half2_rn(fmaxf(c[0], 0.f), fmaxf(c[1], 0.f));
            __half2 v23 = __floats2half2_rn(fmaxf(c[2], 0.f), fmaxf(c[3], 0.f));
            *(__half2*)(smem + (size_t)row * (EP_STRIDE * 2) + col * 2) = v01;
            *(__half2*)(smem + (size_t)(row + 8) * (EP_STRIDE * 2) + col * 2) = v23;
        }
    }
    __syncthreads();
#pragma unroll
    for (int j = 0; j < 8; j++) {
        int lin = tid + j * 256;
        int row = lin >> 4, ch = lin & 15;
        int gm = m0 + row;
        if (gm < Nn) {
            uint4 v = *(const uint4*)(smem + (size_t)row * (EP_STRIDE * 2) + ch * 16);
            *(uint4*)(g_Hh + ((size_t)r * Nn + gm) * Hh + n0 + ch * 8) = v;
        }
    }
}

// ---------------- layer-1 mean: h1 = 0.25 * sum_r Hh[r] (fp16 in/out) -------
__global__ void k_mean() {
    int idx = blockIdx.x * blockDim.x + threadIdx.x;
    const int total = Nn * Hh / 8;   // 8 halfs per uint4
    if (idx >= total) return;
    const uint4* h = (const uint4*)g_Hh;
    size_t off = (size_t)Nn * Hh / 8;
    uint4 a = h[idx], b = h[idx + off], c = h[idx + 2 * off], d = h[idx + 3 * off];
    const __half2* a2 = (const __half2*)&a;
    const __half2* b2 = (const __half2*)&b;
    const __half2* c2 = (const __half2*)&c;
    const __half2* d2 = (const __half2*)&d;
    uint4 o;
    __half2* o2 = (__half2*)&o;
#pragma unroll
    for (int j = 0; j < 4; j++) {
        float2 fa = __half22float2(a2[j]), fb = __half22float2(b2[j]);
        float2 fc = __half22float2(c2[j]), fd = __half22float2(d2[j]);
        o2[j] = __floats2half2_rn(0.25f * (fa.x + fb.x + fc.x + fd.x),
                                  0.25f * (fa.y + fb.y + fc.y + fd.y));
    }
    ((uint4*)g_h1h)[idx] = o;
}

// ---------------- attention + residual fusion + output GEMM -----------------
// Lane owns columns [lane*8, lane*8+8): one uint4 LDG per relation (MLP 4).
__global__ __launch_bounds__(256) void k_attn(const float* __restrict__ att_q,
                                              const float* __restrict__ tau_p,
                                              const float* __restrict__ W_out,
                                              const float* __restrict__ b_out,
                                              float* __restrict__ out) {
    int n = blockIdx.x * 8 + (threadIdx.x >> 5);
    if (n >= Nn) return;
    int lane = threadIdx.x & 31;

    // q for this lane's 8 columns
    float4 q0 = *(const float4*)(att_q + lane * 8);
    float4 q1 = *(const float4*)(att_q + lane * 8 + 4);
    float q[8] = {q0.x, q0.y, q0.z, q0.w, q1.x, q1.y, q1.z, q1.w};

    // issue all 4 relation loads up front (independent)
    uint4 hv[4];
#pragma unroll
    for (int r = 0; r < 4; r++)
        hv[r] = __ldg((const uint4*)(g_Hh + ((size_t)r * Nn + n) * Hh) + lane);

    float v[4][8];
    float sc[4];
#pragma unroll
    for (int r = 0; r < 4; r++) {
        const __half2* h2p = (const __half2*)&hv[r];
        float s = 0.f;
#pragma unroll
        for (int j = 0; j < 4; j++) {
            float2 f = __half22float2(h2p[j]);
            v[r][2 * j] = f.x; v[r][2 * j + 1] = f.y;
            s += f.x * q[2 * j] + f.y * q[2 * j + 1];
        }
#pragma unroll
        for (int o = 16; o; o >>= 1) s += __shfl_xor_sync(0xffffffffu, s, o);
        sc[r] = s;
    }
    float tc = fminf(fmaxf(tau_p[0], 0.5f), 5.0f);
    float inv = 1.0f / tc;
    float s0 = sc[0] * inv, s1 = sc[1] * inv, s2 = sc[2] * inv, s3 = sc[3] * inv;
    float m = fmaxf(fmaxf(s0, s1), fmaxf(s2, s3));
    float e0 = expf(s0 - m), e1 = expf(s1 - m), e2 = expf(s2 - m), e3 = expf(s3 - m);
    float se = e0 + e1 + e2 + e3;
    float al[4] = {e0 / se, e1 / se, e2 / se, e3 / se};

    float h2[8];
#pragma unroll
    for (int k = 0; k < 8; k++)
        h2[k] = (0.25f + al[0]) * v[0][k] + (0.25f + al[1]) * v[1][k] +
                (0.25f + al[2]) * v[2][k] + (0.25f + al[3]) * v[3][k];

    float acc[16];
#pragma unroll
    for (int c = 0; c < 16; c++) acc[c] = 0.f;
#pragma unroll
    for (int k = 0; k < 8; k++) {
        int idx = lane * 8 + k;
        const float4* wr = (const float4*)(W_out + (size_t)idx * 16);
        float4 w0 = wr[0], w1 = wr[1], w2 = wr[2], w3 = wr[3];
        float hvv = h2[k];
        acc[0]  += hvv * w0.x; acc[1]  += hvv * w0.y; acc[2]  += hvv * w0.z; acc[3]  += hvv * w0.w;
        acc[4]  += hvv * w1.x; acc[5]  += hvv * w1.y; acc[6]  += hvv * w1.z; acc[7]  += hvv * w1.w;
        acc[8]  += hvv * w2.x; acc[9]  += hvv * w2.y; acc[10] += hvv * w2.z; acc[11] += hvv * w2.w;
        acc[12] += hvv * w3.x; acc[13] += hvv * w3.y; acc[14] += hvv * w3.z; acc[15] += hvv * w3.w;
    }
#pragma unroll
    for (int c = 0; c < 16; c++)
#pragma unroll
        for (int o = 16; o; o >>= 1) acc[c] += __shfl_xor_sync(0xffffffffu, acc[c], o);

    if (lane < 16) {
        float lg = 0.f;
#pragma unroll
        for (int c = 0; c < 16; c++)
            if (lane == c) lg = acc[c];
        out[(size_t)n * Cc + lane] = lg + b_out[lane];
    }
    if (lane < 4) {
        float a = al[0];
        if (lane == 1) a = al[1];
        if (lane == 2) a = al[2];
        if (lane == 3) a = al[3];
        out[(size_t)Nn * Cc + (size_t)n * Rr + lane] = a;
    }
}

// ---------------- launch (prep overlapped with CSR build) --------------------
extern "C" void kernel_launch(void* const* d_in, const int* in_sizes, int n_in,
                              void* d_out, int out_size) {
    const float* X     = (const float*)d_in[0];
    const int*   EI    = (const int*)d_in[1];
    const float* W1    = (const float*)d_in[2];
    const float* W2    = (const float*)d_in[3];
    const float* att_q = (const float*)d_in[4];
    const float* tau   = (const float*)d_in[5];
    const float* W_out = (const float*)d_in[6];
    const float* b_out = (const float*)d_in[7];
    float* out = (float*)d_out;
    (void)in_sizes; (void)n_in; (void)out_size;

    static cudaStream_t s1 = nullptr;
    static cudaEvent_t evFork, evPrep;
    if (s1 == nullptr) {
        cudaStreamCreateWithFlags(&s1, cudaStreamNonBlocking);
        cudaEventCreateWithFlags(&evFork, cudaEventDisableTiming);
        cudaEventCreateWithFlags(&evPrep, cudaEventDisableTiming);
        cudaFuncSetAttribute(k_gemm, cudaFuncAttributeMaxDynamicSharedMemorySize, SMEM_GEMM);
    }

    // CSR build on stream 0; prep forked onto s1 (capture-legal)
    k_zero_deg<<<(Rr * Nn + 255) / 256, 256>>>();
    cudaEventRecord(evFork, 0);
    cudaStreamWaitEvent(s1, evFork, 0);
    k_prep<<<(XCVT + 2 * WCVT + 255) / 256, 256, 0, s1>>>(X, W1, W2);
    cudaEventRecord(evPrep, s1);

    k_hist<<<(Rr * Ee + 255) / 256, 256>>>(EI);
    k_scan1<<<dim3(NBLK, Rr), 1024>>>();
    k_scan2<<<1, 128>>>();
    k_scan3<<<dim3(NBLK, Rr), 1024>>>();
    k_scatter<<<(Rr * Ee + 255) / 256, 256>>>(EI);
    cudaStreamWaitEvent(0, evPrep, 0);

    dim3 spmm_grid((Nn + 7) / 8, Rr);
    dim3 gemm_grid((Nn + 127) / 128, Hh / 128, Rr);

    // Layer 1
    k_spmm<<<spmm_grid, 256>>>(0);
    k_gemm<<<gemm_grid, 256, SMEM_GEMM>>>(0);
    k_mean<<<(Nn * Hh / 8 + 255) / 256, 256>>>();

    // Layer 2
    k_spmm<<<spmm_grid, 256>>>(1);
    k_gemm<<<gemm_grid, 256, SMEM_GEMM>>>(1);

    // Attention + output head
    k_attn<<<(Nn + 7) / 8, 256>>>(att_q, tau, W_out, b_out, out);
}